// round 5
// baseline (speedup 1.0000x reference)
#include <cuda_runtime.h>
#include <cuda_bf16.h>
#include <math.h>
#include <stdint.h>

// ---------------------------------------------------------------------------
// Encoder layer: B=1, S=4096, D=1024, H=16, dk=64, F=4096, fp32 in/out.
// tf32 mma.sync everywhere (tcgen05 not available: harness PTX target lacks
// the sm_103a suffix). R5: BK=32 GEMM w/ single barrier per tile, fused QKV.
// ---------------------------------------------------------------------------

#define S_LEN 4096
#define D_MODEL 1024
#define D_FF 4096
#define NUM_HEADS 16
#define DK 64
#define QKV_LD 3072

__device__ float g_h1[S_LEN * D_MODEL];
__device__ float g_QKV[S_LEN * QKV_LD];
__device__ float g_ctx[S_LEN * D_MODEL];
__device__ float g_x1[S_LEN * D_MODEL];
__device__ float g_h2[S_LEN * D_MODEL];
__device__ float g_f1[S_LEN * D_FF];
__device__ float g_W3[D_MODEL * QKV_LD];
__device__ float g_b3[QKV_LD];

// ---------------------------------------------------------------------------
__device__ __forceinline__ void mma_tf32(float (&d)[4],
    const uint32_t (&a)[4], uint32_t b0, uint32_t b1)
{
    asm volatile(
        "mma.sync.aligned.m16n8k8.row.col.f32.tf32.tf32.f32 "
        "{%0,%1,%2,%3}, {%4,%5,%6,%7}, {%8,%9}, {%0,%1,%2,%3};\n"
        : "+f"(d[0]), "+f"(d[1]), "+f"(d[2]), "+f"(d[3])
        : "r"(a[0]), "r"(a[1]), "r"(a[2]), "r"(a[3]), "r"(b0), "r"(b1));
}
__device__ __forceinline__ uint32_t f2u(float x) { return __float_as_uint(x); }
__device__ __forceinline__ uint32_t smem_u32(const void* p) {
    return (uint32_t)__cvta_generic_to_shared(p);
}
#define CP_ASYNC16(dst, src) \
    asm volatile("cp.async.cg.shared.global [%0], [%1], 16;\n" :: "r"(dst), "l"(src))
#define CP_COMMIT() asm volatile("cp.async.commit_group;\n")
#define CP_WAIT(n)  asm volatile("cp.async.wait_group %0;\n" :: "n"(n))

// 2^t for t <= 0, FMA pipe only
__device__ __forceinline__ float exp2p(float t) {
    t = fmaxf(t, -126.0f);
    float fi = floorf(t);
    float f  = t - fi;
    float p = 1.5403530e-4f;
    p = fmaf(p, f, 1.3333558e-3f);
    p = fmaf(p, f, 9.6181291e-3f);
    p = fmaf(p, f, 5.5504109e-2f);
    p = fmaf(p, f, 2.4022651e-1f);
    p = fmaf(p, f, 6.9314718e-1f);
    p = fmaf(p, f, 1.0f);
    return p * __int_as_float(((int)fi + 127) << 23);
}

// ---------------------------------------------------------------------------
// Concat Wq|Wk|Wv -> W3 [1024, 3072], bq|bk|bv -> b3 [3072]
// ---------------------------------------------------------------------------
__global__ __launch_bounds__(256) void concat3(
    const float* __restrict__ Wq, const float* __restrict__ Wk,
    const float* __restrict__ Wv, const float* __restrict__ bq,
    const float* __restrict__ bk, const float* __restrict__ bv,
    float* __restrict__ W3, float* __restrict__ b3)
{
    const int idx = blockIdx.x * 256 + threadIdx.x;
    const int k = idx / QKV_LD, n = idx % QKV_LD;
    const int sel = n >> 10, col = n & 1023;
    const float* W = sel == 0 ? Wq : (sel == 1 ? Wk : Wv);
    W3[idx] = W[k * D_MODEL + col];
    if (idx < QKV_LD) {
        const float* b = sel == 0 ? bq : (sel == 1 ? bk : bv);
        b3[idx] = b[col];
    }
}

// ---------------------------------------------------------------------------
// LayerNorm (unbiased var ddof=1, denom = sqrt(var)+eps)
// ---------------------------------------------------------------------------
__global__ __launch_bounds__(256) void ln_kernel(
    const float* __restrict__ x, const float* __restrict__ alpha,
    const float* __restrict__ beta, float* __restrict__ y)
{
    const int row = blockIdx.x;
    const float4* xr = (const float4*)(x + (size_t)row * D_MODEL);
    float4* yr = (float4*)(y + (size_t)row * D_MODEL);
    const int tid = threadIdx.x;

    float4 xl = xr[tid];
    float s = xl.x + xl.y + xl.z + xl.w;

    __shared__ float sh[8];
#pragma unroll
    for (int o = 16; o > 0; o >>= 1) s += __shfl_xor_sync(0xffffffffu, s, o);
    if ((tid & 31) == 0) sh[tid >> 5] = s;
    __syncthreads();
    float mu = 0.f;
#pragma unroll
    for (int i = 0; i < 8; i++) mu += sh[i];
    mu *= (1.0f / D_MODEL);
    __syncthreads();

    float dx = xl.x - mu, dy = xl.y - mu, dz = xl.z - mu, dw = xl.w - mu;
    float v = dx * dx + dy * dy + dz * dz + dw * dw;
#pragma unroll
    for (int o = 16; o > 0; o >>= 1) v += __shfl_xor_sync(0xffffffffu, v, o);
    if ((tid & 31) == 0) sh[tid >> 5] = v;
    __syncthreads();
    float var = 0.f;
#pragma unroll
    for (int i = 0; i < 8; i++) var += sh[i];
    var *= (1.0f / (D_MODEL - 1));

    const float a = alpha[0], b = beta[0];
    const float inv = a / (sqrtf(var) + 1e-6f);
    float4 o;
    o.x = dx * inv + b; o.y = dy * inv + b;
    o.z = dz * inv + b; o.w = dw * inv + b;
    yr[tid] = o;
}

// ---------------------------------------------------------------------------
// TF32 GEMM: C[M,N] = A[M,K] @ W[K,N] + bias (+relu) (+residual)
// BM=128 BN=128 BK=32, 256 threads (8 warps, 64x32 warp tiles),
// 3-stage cp.async pipeline, ONE barrier per k-tile (CUTLASS ordering),
// 2 CTAs/SM.
// ---------------------------------------------------------------------------
#define ASTR 36                      // A tile row stride (floats): bank CF
#define BSTR 136                     // B tile row stride (floats): bank CF
#define A_TILE (128 * ASTR)
#define B_TILE (32 * BSTR)
#define STG_F  (A_TILE + B_TILE)
#define MM_SMEM (3 * STG_F * 4)

template<bool RELU, bool RES>
__global__ __launch_bounds__(256, 2) void mm_tf32(
    const float* __restrict__ A, const float* __restrict__ W,
    const float* __restrict__ bias, const float* __restrict__ Rsd,
    float* __restrict__ C, int M, int N, int K)
{
    extern __shared__ float smg[];

    const int tid  = threadIdx.x;
    const int warp = tid >> 5, lane = tid & 31;
    const int r = lane >> 2, c = lane & 3;
    const int wm = (warp >> 2) * 64, wn = (warp & 3) * 32;
    const int m0 = blockIdx.y * 128, n0 = blockIdx.x * 128;

    const uint32_t s0 = smem_u32(smg);

    float acc[4][4][4];
#pragma unroll
    for (int i = 0; i < 4; i++)
#pragma unroll
        for (int j = 0; j < 4; j++)
#pragma unroll
            for (int k = 0; k < 4; k++) acc[i][j][k] = 0.f;

    const int NK = K >> 5;   // 32-wide k-tiles (K is 1024 or 4096 -> NK>=32)

    // tile loader: A 128x32 (1024 16B chunks), B 32x128 (1024 chunks)
    auto load_tile = [&](int kt, int st) {
        const uint32_t ab = s0 + (uint32_t)(st * STG_F) * 4u;
        const uint32_t bb = ab + (uint32_t)A_TILE * 4u;
#pragma unroll
        for (int i = 0; i < 4; i++) {
            const int id = tid + 256 * i;
            const int ar = id >> 3, akc = id & 7;
            CP_ASYNC16(ab + (uint32_t)(ar * ASTR + akc * 4) * 4u,
                       A + (size_t)(m0 + ar) * K + kt * 32 + akc * 4);
            const int br = id >> 5, bnc = id & 31;
            CP_ASYNC16(bb + (uint32_t)(br * BSTR + bnc * 4) * 4u,
                       W + (size_t)(kt * 32 + br) * N + n0 + bnc * 4);
        }
    };

    // prologue: tiles 0,1 -> stages 0,1
    load_tile(0, 0);
    CP_COMMIT();
    load_tile(1, 1);
    CP_COMMIT();

    for (int kt = 0; kt < NK; kt++) {
        const int st = kt - (kt / 3) * 3;
        CP_WAIT(1);                 // tile kt complete (this thread)
        __syncthreads();            // all threads: tile kt ready; prior reads done
        if (kt + 2 < NK) {
            const int s2 = (kt + 2) - ((kt + 2) / 3) * 3;
            load_tile(kt + 2, s2);  // overwrites stage read 2 iters ago: safe
        }
        CP_COMMIT();

        const float* Ab = smg + st * STG_F;
        const float* Bb = Ab + A_TILE;
#pragma unroll
        for (int ks = 0; ks < 4; ks++) {
            uint32_t a[4][4], b[4][2];
#pragma unroll
            for (int fm = 0; fm < 4; fm++) {
                const float* p = Ab + (wm + fm * 16 + r) * ASTR + ks * 8 + c;
                a[fm][0] = f2u(p[0]);
                a[fm][1] = f2u(p[8 * ASTR]);
                a[fm][2] = f2u(p[4]);
                a[fm][3] = f2u(p[8 * ASTR + 4]);
            }
#pragma unroll
            for (int fn = 0; fn < 4; fn++) {
                const float* q = Bb + (ks * 8 + c) * BSTR + wn + fn * 8 + r;
                b[fn][0] = f2u(q[0]);
                b[fn][1] = f2u(q[4 * BSTR]);
            }
#pragma unroll
            for (int fm = 0; fm < 4; fm++)
#pragma unroll
                for (int fn = 0; fn < 4; fn++)
                    mma_tf32(acc[fm][fn], a[fm], b[fn][0], b[fn][1]);
        }
    }

    // epilogue
#pragma unroll
    for (int fm = 0; fm < 4; fm++) {
        const int row0 = m0 + wm + fm * 16 + r;
        const int row1 = row0 + 8;
#pragma unroll
        for (int fn = 0; fn < 4; fn++) {
            const int col = n0 + wn + fn * 8 + 2 * c;
            float2 bi = *(const float2*)&bias[col];
            float v0 = acc[fm][fn][0] + bi.x;
            float v1 = acc[fm][fn][1] + bi.y;
            float v2 = acc[fm][fn][2] + bi.x;
            float v3 = acc[fm][fn][3] + bi.y;
            if (RELU) {
                v0 = fmaxf(v0, 0.f); v1 = fmaxf(v1, 0.f);
                v2 = fmaxf(v2, 0.f); v3 = fmaxf(v3, 0.f);
            }
            if (RES) {
                float2 r0 = *(const float2*)&Rsd[(size_t)row0 * N + col];
                float2 r1 = *(const float2*)&Rsd[(size_t)row1 * N + col];
                v0 += r0.x; v1 += r0.y; v2 += r1.x; v3 += r1.y;
            }
            *(float2*)&C[(size_t)row0 * N + col] = make_float2(v0, v1);
            *(float2*)&C[(size_t)row1 * N + col] = make_float2(v2, v3);
        }
    }
}

// ---------------------------------------------------------------------------
// Flash attention, tf32 mma.sync. grid = (S/256, H), 256 threads (8 warps).
// Reads packed QKV [S, 3072] (Q at +0, K at +1024, V at +2048).
// ---------------------------------------------------------------------------
#define QSTR 68
#define KSTR 68
#define VSTR 72
#define K_TILE (64 * KSTR)
#define V_TILE (64 * VSTR)
#define ATT_SMEM ((256 * QSTR + 2 * K_TILE + 2 * V_TILE) * 4)
#define QK_SCALE 0.1803368801111364f    // 0.125 * log2(e)

__global__ __launch_bounds__(256, 1) void attn_tf32(
    const float* __restrict__ QKV, float* __restrict__ Ctx)
{
    extern __shared__ float sm[];
    float* QP = sm;                          // [256][QSTR]: Q staging, then P
    float* Ks = QP + 256 * QSTR;             // [2][64][KSTR]
    float* Vs = Ks + 2 * K_TILE;             // [2][64][VSTR]

    const int tid  = threadIdx.x;
    const int warp = tid >> 5, lane = tid & 31;
    const int r = lane >> 2, c = lane & 3;
    const int wr = warp * 32;
    const int qb = blockIdx.x, h = blockIdx.y;
    const int cb = h * DK;

    const float* Qm = QKV;
    const float* Km = QKV + 1024;
    const float* Vm = QKV + 2048;

    {
        const uint32_t qdst = smem_u32(QP);
#pragma unroll
        for (int i = 0; i < 16; i++) {
            int id = tid + 256 * i;
            int row = id >> 4, ch = id & 15;
            CP_ASYNC16(qdst + (uint32_t)(row * QSTR + ch * 4) * 4u,
                       Qm + (size_t)(qb * 256 + row) * QKV_LD + cb + ch * 4);
        }
        CP_COMMIT();
        CP_WAIT(0);
        __syncthreads();
    }

    uint32_t qf[2][8][4];
#pragma unroll
    for (int fm = 0; fm < 2; fm++)
#pragma unroll
        for (int ks = 0; ks < 8; ks++) {
            const float* p = QP + (wr + fm * 16 + r) * QSTR + ks * 8 + c;
            qf[fm][ks][0] = f2u(p[0] * QK_SCALE);
            qf[fm][ks][1] = f2u(p[8 * QSTR] * QK_SCALE);
            qf[fm][ks][2] = f2u(p[4] * QK_SCALE);
            qf[fm][ks][3] = f2u(p[8 * QSTR + 4] * QK_SCALE);
        }
    __syncthreads();

    float mrow[2][2] = {{-1e30f, -1e30f}, {-1e30f, -1e30f}};
    float lrow[2][2] = {{0.f, 0.f}, {0.f, 0.f}};
    float acc[2][8][4];
#pragma unroll
    for (int i = 0; i < 2; i++)
#pragma unroll
        for (int j = 0; j < 8; j++)
#pragma unroll
            for (int k = 0; k < 4; k++) acc[i][j][k] = 0.f;

    const uint32_t kdst = smem_u32(Ks);
    const uint32_t vdst = smem_u32(Vs);

#pragma unroll
    for (int i = 0; i < 4; i++) {
        int id = tid + 256 * i;
        int row = id >> 4, ch = id & 15;
        size_t g = (size_t)row * QKV_LD + cb + ch * 4;
        CP_ASYNC16(kdst + (uint32_t)(row * KSTR + ch * 4) * 4u, Km + g);
        CP_ASYNC16(vdst + (uint32_t)(row * VSTR + ch * 4) * 4u, Vm + g);
    }
    CP_COMMIT();

    for (int kt = 0; kt < S_LEN / 64; kt++) {
        const int buf = kt & 1;
        if (kt + 1 < S_LEN / 64) {
            const int nb = buf ^ 1;
#pragma unroll
            for (int i = 0; i < 4; i++) {
                int id = tid + 256 * i;
                int row = id >> 4, ch = id & 15;
                size_t g = (size_t)((kt + 1) * 64 + row) * QKV_LD + cb + ch * 4;
                CP_ASYNC16(kdst + (uint32_t)(nb * K_TILE + row * KSTR + ch * 4) * 4u, Km + g);
                CP_ASYNC16(vdst + (uint32_t)(nb * V_TILE + row * VSTR + ch * 4) * 4u, Vm + g);
            }
        }
        CP_COMMIT();
        CP_WAIT(1);
        __syncthreads();

        float s[2][8][4];
#pragma unroll
        for (int i = 0; i < 2; i++)
#pragma unroll
            for (int j = 0; j < 8; j++)
#pragma unroll
                for (int k = 0; k < 4; k++) s[i][j][k] = 0.f;

        const float* Kb = Ks + buf * K_TILE;
#pragma unroll
        for (int ks = 0; ks < 8; ks++) {
#pragma unroll
            for (int fn = 0; fn < 8; fn++) {
                const float* kp = Kb + (fn * 8 + r) * KSTR + ks * 8 + c;
                const uint32_t b0 = f2u(kp[0]);
                const uint32_t b1 = f2u(kp[4]);
                mma_tf32(s[0][fn], qf[0][ks], b0, b1);
                mma_tf32(s[1][fn], qf[1][ks], b0, b1);
            }
        }

#pragma unroll
        for (int fm = 0; fm < 2; fm++) {
            float mx0 = -1e30f, mx1 = -1e30f;
#pragma unroll
            for (int fn = 0; fn < 8; fn++) {
                mx0 = fmaxf(mx0, fmaxf(s[fm][fn][0], s[fm][fn][1]));
                mx1 = fmaxf(mx1, fmaxf(s[fm][fn][2], s[fm][fn][3]));
            }
            mx0 = fmaxf(mx0, __shfl_xor_sync(0xffffffffu, mx0, 1));
            mx0 = fmaxf(mx0, __shfl_xor_sync(0xffffffffu, mx0, 2));
            mx1 = fmaxf(mx1, __shfl_xor_sync(0xffffffffu, mx1, 1));
            mx1 = fmaxf(mx1, __shfl_xor_sync(0xffffffffu, mx1, 2));

            const float mn0 = fmaxf(mrow[fm][0], mx0);
            const float mn1 = fmaxf(mrow[fm][1], mx1);
            const float sc0 = exp2p(mrow[fm][0] - mn0);
            const float sc1 = exp2p(mrow[fm][1] - mn1);
            float ls0 = 0.f, ls1 = 0.f;
#pragma unroll
            for (int fn = 0; fn < 8; fn++) {
                s[fm][fn][0] = exp2p(s[fm][fn][0] - mn0);
                s[fm][fn][1] = exp2p(s[fm][fn][1] - mn0);
                s[fm][fn][2] = exp2p(s[fm][fn][2] - mn1);
                s[fm][fn][3] = exp2p(s[fm][fn][3] - mn1);
                ls0 += s[fm][fn][0] + s[fm][fn][1];
                ls1 += s[fm][fn][2] + s[fm][fn][3];
            }
            ls0 += __shfl_xor_sync(0xffffffffu, ls0, 1);
            ls0 += __shfl_xor_sync(0xffffffffu, ls0, 2);
            ls1 += __shfl_xor_sync(0xffffffffu, ls1, 1);
            ls1 += __shfl_xor_sync(0xffffffffu, ls1, 2);

            lrow[fm][0] = lrow[fm][0] * sc0 + ls0;
            lrow[fm][1] = lrow[fm][1] * sc1 + ls1;
            mrow[fm][0] = mn0; mrow[fm][1] = mn1;

#pragma unroll
            for (int fn = 0; fn < 8; fn++) {
                acc[fm][fn][0] *= sc0; acc[fm][fn][1] *= sc0;
                acc[fm][fn][2] *= sc1; acc[fm][fn][3] *= sc1;
            }
#pragma unroll
            for (int fn = 0; fn < 8; fn++) {
                *(float2*)&QP[(wr + fm * 16 + r) * QSTR + fn * 8 + 2 * c] =
                    make_float2(s[fm][fn][0], s[fm][fn][1]);
                *(float2*)&QP[(wr + fm * 16 + r + 8) * QSTR + fn * 8 + 2 * c] =
                    make_float2(s[fm][fn][2], s[fm][fn][3]);
            }
        }
        __syncwarp();

        const float* Vb = Vs + buf * V_TILE;
#pragma unroll
        for (int ks = 0; ks < 8; ks++) {
            uint32_t pa[2][4];
#pragma unroll
            for (int fm = 0; fm < 2; fm++) {
                const float* pp = QP + (wr + fm * 16 + r) * QSTR + ks * 8 + c;
                pa[fm][0] = f2u(pp[0]);
                pa[fm][1] = f2u(pp[8 * QSTR]);
                pa[fm][2] = f2u(pp[4]);
                pa[fm][3] = f2u(pp[8 * QSTR + 4]);
            }
#pragma unroll
            for (int fn = 0; fn < 8; fn++) {
                const float* vp = Vb + (ks * 8 + c) * VSTR + fn * 8 + r;
                const uint32_t b0 = f2u(vp[0]);
                const uint32_t b1 = f2u(vp[4 * VSTR]);
                mma_tf32(acc[0][fn], pa[0], b0, b1);
                mma_tf32(acc[1][fn], pa[1], b0, b1);
            }
        }
        __syncthreads();
    }

#pragma unroll
    for (int fm = 0; fm < 2; fm++) {
        const float inv0 = 1.f / lrow[fm][0];
        const float inv1 = 1.f / lrow[fm][1];
        const int row0 = qb * 256 + wr + fm * 16 + r;
        const int row1 = row0 + 8;
#pragma unroll
        for (int fn = 0; fn < 8; fn++) {
            const int col = cb + fn * 8 + 2 * c;
            *(float2*)&Ctx[(size_t)row0 * D_MODEL + col] =
                make_float2(acc[fm][fn][0] * inv0, acc[fm][fn][1] * inv0);
            *(float2*)&Ctx[(size_t)row1 * D_MODEL + col] =
                make_float2(acc[fm][fn][2] * inv1, acc[fm][fn][3] * inv1);
        }
    }
}

// ---------------------------------------------------------------------------
extern "C" void kernel_launch(void* const* d_in, const int* in_sizes, int n_in,
                              void* d_out, int out_size)
{
    const float* x    = (const float*)d_in[0];
    const float* Wq   = (const float*)d_in[1];
    const float* bq   = (const float*)d_in[2];
    const float* Wk   = (const float*)d_in[3];
    const float* bk   = (const float*)d_in[4];
    const float* Wv   = (const float*)d_in[5];
    const float* bv   = (const float*)d_in[6];
    const float* Wo   = (const float*)d_in[7];
    const float* bo   = (const float*)d_in[8];
    const float* ln1a = (const float*)d_in[9];
    const float* ln1b = (const float*)d_in[10];
    const float* W1   = (const float*)d_in[11];
    const float* b1   = (const float*)d_in[12];
    const float* W2   = (const float*)d_in[13];
    const float* b2   = (const float*)d_in[14];
    const float* ln2a = (const float*)d_in[15];
    const float* ln2b = (const float*)d_in[16];
    float* out = (float*)d_out;

    float *h1, *QKV, *ctx, *x1, *h2, *f1, *W3, *b3;
    cudaGetSymbolAddress((void**)&h1,  g_h1);
    cudaGetSymbolAddress((void**)&QKV, g_QKV);
    cudaGetSymbolAddress((void**)&ctx, g_ctx);
    cudaGetSymbolAddress((void**)&x1,  g_x1);
    cudaGetSymbolAddress((void**)&h2,  g_h2);
    cudaGetSymbolAddress((void**)&f1,  g_f1);
    cudaGetSymbolAddress((void**)&W3,  g_W3);
    cudaGetSymbolAddress((void**)&b3,  g_b3);

    cudaFuncSetAttribute(mm_tf32<false, false>,
                         cudaFuncAttributeMaxDynamicSharedMemorySize, MM_SMEM);
    cudaFuncSetAttribute(mm_tf32<false, true>,
                         cudaFuncAttributeMaxDynamicSharedMemorySize, MM_SMEM);
    cudaFuncSetAttribute(mm_tf32<true, false>,
                         cudaFuncAttributeMaxDynamicSharedMemorySize, MM_SMEM);
    cudaFuncSetAttribute(attn_tf32,
                         cudaFuncAttributeMaxDynamicSharedMemorySize, ATT_SMEM);

    // fuse QKV weights/biases
    concat3<<<(D_MODEL * QKV_LD) / 256, 256>>>(Wq, Wk, Wv, bq, bk, bv, W3, b3);

    const dim3 gQKV (QKV_LD / 128, S_LEN / 128);     // (24, 32)
    const dim3 gSmall(D_MODEL / 128, S_LEN / 128);   // (8, 32)
    const dim3 gFF1 (D_FF   / 128, S_LEN / 128);     // (32, 32)

    // residual 1
    ln_kernel<<<S_LEN, 256>>>(x, ln1a, ln1b, h1);
    mm_tf32<false, false><<<gQKV, 256, MM_SMEM>>>(h1, W3, b3, nullptr, QKV, S_LEN, QKV_LD, D_MODEL);
    attn_tf32<<<dim3(S_LEN / 256, NUM_HEADS), 256, ATT_SMEM>>>(QKV, ctx);
    mm_tf32<false, true><<<gSmall, 256, MM_SMEM>>>(ctx, Wo, bo, x, x1, S_LEN, D_MODEL, D_MODEL);

    // residual 2
    ln_kernel<<<S_LEN, 256>>>(x1, ln2a, ln2b, h2);
    mm_tf32<true,  false><<<gFF1, 256, MM_SMEM>>>(h2, W1, b1, nullptr, f1, S_LEN, D_FF, D_MODEL);
    mm_tf32<false, true><<<gSmall, 256, MM_SMEM>>>(f1, W2, b2, x1, out, S_LEN, D_MODEL, D_FF);
}

// round 6
// speedup vs baseline: 1.5212x; 1.5212x over previous
#include <cuda_runtime.h>
#include <cuda_bf16.h>
#include <math.h>
#include <stdint.h>

// ---------------------------------------------------------------------------
// Encoder layer: B=1, S=4096, D=1024, H=16, dk=64, F=4096, fp32 in/out.
// tf32 mma.sync everywhere. R6: fused QKV GEMM with split outputs;
// attention fm=1 / 2 CTAs/SM / shuffle-based P conversion.
// ---------------------------------------------------------------------------

#define S_LEN 4096
#define D_MODEL 1024
#define D_FF 4096
#define NUM_HEADS 16
#define DK 64
#define QKV_N 3072

__device__ float g_h1[S_LEN * D_MODEL];
__device__ float g_Q [S_LEN * D_MODEL];
__device__ float g_K [S_LEN * D_MODEL];
__device__ float g_V [S_LEN * D_MODEL];
__device__ float g_ctx[S_LEN * D_MODEL];
__device__ float g_x1[S_LEN * D_MODEL];
__device__ float g_h2[S_LEN * D_MODEL];
__device__ float g_f1[S_LEN * D_FF];
__device__ float g_W3[D_MODEL * QKV_N];
__device__ float g_b3[QKV_N];

// ---------------------------------------------------------------------------
__device__ __forceinline__ void mma_tf32(float (&d)[4],
    const uint32_t (&a)[4], uint32_t b0, uint32_t b1)
{
    asm volatile(
        "mma.sync.aligned.m16n8k8.row.col.f32.tf32.tf32.f32 "
        "{%0,%1,%2,%3}, {%4,%5,%6,%7}, {%8,%9}, {%0,%1,%2,%3};\n"
        : "+f"(d[0]), "+f"(d[1]), "+f"(d[2]), "+f"(d[3])
        : "r"(a[0]), "r"(a[1]), "r"(a[2]), "r"(a[3]), "r"(b0), "r"(b1));
}
__device__ __forceinline__ uint32_t f2u(float x) { return __float_as_uint(x); }
__device__ __forceinline__ uint32_t smem_u32(const void* p) {
    return (uint32_t)__cvta_generic_to_shared(p);
}
#define CP_ASYNC16(dst, src) \
    asm volatile("cp.async.cg.shared.global [%0], [%1], 16;\n" :: "r"(dst), "l"(src))
#define CP_COMMIT() asm volatile("cp.async.commit_group;\n")
#define CP_WAIT(n)  asm volatile("cp.async.wait_group %0;\n" :: "n"(n))

// 2^t for t <= 0, FMA pipe only
__device__ __forceinline__ float exp2p(float t) {
    t = fmaxf(t, -126.0f);
    float fi = floorf(t);
    float f  = t - fi;
    float p = 1.5403530e-4f;
    p = fmaf(p, f, 1.3333558e-3f);
    p = fmaf(p, f, 9.6181291e-3f);
    p = fmaf(p, f, 5.5504109e-2f);
    p = fmaf(p, f, 2.4022651e-1f);
    p = fmaf(p, f, 6.9314718e-1f);
    p = fmaf(p, f, 1.0f);
    return p * __int_as_float(((int)fi + 127) << 23);
}

// ---------------------------------------------------------------------------
// Concat Wq|Wk|Wv -> W3 [1024, 3072], bq|bk|bv -> b3 [3072]
// ---------------------------------------------------------------------------
__global__ __launch_bounds__(256) void concat3(
    const float* __restrict__ Wq, const float* __restrict__ Wk,
    const float* __restrict__ Wv, const float* __restrict__ bq,
    const float* __restrict__ bk, const float* __restrict__ bv,
    float* __restrict__ W3, float* __restrict__ b3)
{
    const int idx = blockIdx.x * 256 + threadIdx.x;
    const int k = idx / QKV_N, n = idx % QKV_N;
    const int sel = n >> 10, col = n & 1023;
    const float* W = sel == 0 ? Wq : (sel == 1 ? Wk : Wv);
    W3[idx] = W[k * D_MODEL + col];
    if (idx < QKV_N) {
        const float* b = sel == 0 ? bq : (sel == 1 ? bk : bv);
        b3[idx] = b[col];
    }
}

// ---------------------------------------------------------------------------
// LayerNorm (unbiased var ddof=1, denom = sqrt(var)+eps)
// ---------------------------------------------------------------------------
__global__ __launch_bounds__(256) void ln_kernel(
    const float* __restrict__ x, const float* __restrict__ alpha,
    const float* __restrict__ beta, float* __restrict__ y)
{
    const int row = blockIdx.x;
    const float4* xr = (const float4*)(x + (size_t)row * D_MODEL);
    float4* yr = (float4*)(y + (size_t)row * D_MODEL);
    const int tid = threadIdx.x;

    float4 xl = xr[tid];
    float s = xl.x + xl.y + xl.z + xl.w;

    __shared__ float sh[8];
#pragma unroll
    for (int o = 16; o > 0; o >>= 1) s += __shfl_xor_sync(0xffffffffu, s, o);
    if ((tid & 31) == 0) sh[tid >> 5] = s;
    __syncthreads();
    float mu = 0.f;
#pragma unroll
    for (int i = 0; i < 8; i++) mu += sh[i];
    mu *= (1.0f / D_MODEL);
    __syncthreads();

    float dx = xl.x - mu, dy = xl.y - mu, dz = xl.z - mu, dw = xl.w - mu;
    float v = dx * dx + dy * dy + dz * dz + dw * dw;
#pragma unroll
    for (int o = 16; o > 0; o >>= 1) v += __shfl_xor_sync(0xffffffffu, v, o);
    if ((tid & 31) == 0) sh[tid >> 5] = v;
    __syncthreads();
    float var = 0.f;
#pragma unroll
    for (int i = 0; i < 8; i++) var += sh[i];
    var *= (1.0f / (D_MODEL - 1));

    const float a = alpha[0], b = beta[0];
    const float inv = a / (sqrtf(var) + 1e-6f);
    float4 o;
    o.x = dx * inv + b; o.y = dy * inv + b;
    o.z = dz * inv + b; o.w = dw * inv + b;
    yr[tid] = o;
}

// ---------------------------------------------------------------------------
// TF32 GEMM: C = A[M,K] @ W[K,N] + bias (+relu) (+residual)
// BM=128 BN=128 BK=32, 256 threads, 3-stage cp.async, 1 barrier/k-tile,
// 2 CTAs/SM. If C1 != nullptr: N=3072 split into three [M,1024] outputs.
// ---------------------------------------------------------------------------
#define ASTR 36
#define BSTR 136
#define A_TILE (128 * ASTR)
#define B_TILE (32 * BSTR)
#define STG_F  (A_TILE + B_TILE)
#define MM_SMEM (3 * STG_F * 4)

template<bool RELU, bool RES>
__global__ __launch_bounds__(256, 2) void mm_tf32(
    const float* __restrict__ A, const float* __restrict__ W,
    const float* __restrict__ bias, const float* __restrict__ Rsd,
    float* __restrict__ C0, float* __restrict__ C1, float* __restrict__ C2,
    int M, int N, int K)
{
    extern __shared__ float smg[];

    const int tid  = threadIdx.x;
    const int warp = tid >> 5, lane = tid & 31;
    const int r = lane >> 2, c = lane & 3;
    const int wm = (warp >> 2) * 64, wn = (warp & 3) * 32;
    const int m0 = blockIdx.y * 128, n0 = blockIdx.x * 128;

    const uint32_t s0 = smem_u32(smg);

    float acc[4][4][4];
#pragma unroll
    for (int i = 0; i < 4; i++)
#pragma unroll
        for (int j = 0; j < 4; j++)
#pragma unroll
            for (int k = 0; k < 4; k++) acc[i][j][k] = 0.f;

    const int NK = K >> 5;

    auto load_tile = [&](int kt, int st) {
        const uint32_t ab = s0 + (uint32_t)(st * STG_F) * 4u;
        const uint32_t bb = ab + (uint32_t)A_TILE * 4u;
#pragma unroll
        for (int i = 0; i < 4; i++) {
            const int id = tid + 256 * i;
            const int ar = id >> 3, akc = id & 7;
            CP_ASYNC16(ab + (uint32_t)(ar * ASTR + akc * 4) * 4u,
                       A + (size_t)(m0 + ar) * K + kt * 32 + akc * 4);
            const int br = id >> 5, bnc = id & 31;
            CP_ASYNC16(bb + (uint32_t)(br * BSTR + bnc * 4) * 4u,
                       W + (size_t)(kt * 32 + br) * N + n0 + bnc * 4);
        }
    };

    load_tile(0, 0);
    CP_COMMIT();
    load_tile(1, 1);
    CP_COMMIT();

    for (int kt = 0; kt < NK; kt++) {
        const int st = kt - (kt / 3) * 3;
        CP_WAIT(1);
        __syncthreads();
        if (kt + 2 < NK) {
            const int s2 = (kt + 2) - ((kt + 2) / 3) * 3;
            load_tile(kt + 2, s2);
        }
        CP_COMMIT();

        const float* Ab = smg + st * STG_F;
        const float* Bb = Ab + A_TILE;
#pragma unroll
        for (int ks = 0; ks < 4; ks++) {
            uint32_t a[4][4], b[4][2];
#pragma unroll
            for (int fm = 0; fm < 4; fm++) {
                const float* p = Ab + (wm + fm * 16 + r) * ASTR + ks * 8 + c;
                a[fm][0] = f2u(p[0]);
                a[fm][1] = f2u(p[8 * ASTR]);
                a[fm][2] = f2u(p[4]);
                a[fm][3] = f2u(p[8 * ASTR + 4]);
            }
#pragma unroll
            for (int fn = 0; fn < 4; fn++) {
                const float* q = Bb + (ks * 8 + c) * BSTR + wn + fn * 8 + r;
                b[fn][0] = f2u(q[0]);
                b[fn][1] = f2u(q[4 * BSTR]);
            }
#pragma unroll
            for (int fm = 0; fm < 4; fm++)
#pragma unroll
                for (int fn = 0; fn < 4; fn++)
                    mma_tf32(acc[fm][fn], a[fm], b[fn][0], b[fn][1]);
        }
    }

    // output select (QKV split or single)
    float* Cc;
    int nl0, ldc;
    if (C1 != nullptr) {
        const int sel = n0 >> 10;
        Cc  = sel == 0 ? C0 : (sel == 1 ? C1 : C2);
        nl0 = n0 & 1023;
        ldc = 1024;
    } else {
        Cc = C0; nl0 = n0; ldc = N;
    }

#pragma unroll
    for (int fm = 0; fm < 4; fm++) {
        const int row0 = m0 + wm + fm * 16 + r;
        const int row1 = row0 + 8;
#pragma unroll
        for (int fn = 0; fn < 4; fn++) {
            const int colg = n0 + wn + fn * 8 + 2 * c;     // bias index
            const int col  = nl0 + wn + fn * 8 + 2 * c;    // output index
            float2 bi = *(const float2*)&bias[colg];
            float v0 = acc[fm][fn][0] + bi.x;
            float v1 = acc[fm][fn][1] + bi.y;
            float v2 = acc[fm][fn][2] + bi.x;
            float v3 = acc[fm][fn][3] + bi.y;
            if (RELU) {
                v0 = fmaxf(v0, 0.f); v1 = fmaxf(v1, 0.f);
                v2 = fmaxf(v2, 0.f); v3 = fmaxf(v3, 0.f);
            }
            if (RES) {
                float2 r0 = *(const float2*)&Rsd[(size_t)row0 * ldc + col];
                float2 r1 = *(const float2*)&Rsd[(size_t)row1 * ldc + col];
                v0 += r0.x; v1 += r0.y; v2 += r1.x; v3 += r1.y;
            }
            *(float2*)&Cc[(size_t)row0 * ldc + col] = make_float2(v0, v1);
            *(float2*)&Cc[(size_t)row1 * ldc + col] = make_float2(v2, v3);
        }
    }
}

// ---------------------------------------------------------------------------
// Flash attention, tf32 mma.sync. grid = (S/128, H), 256 threads (8 warps),
// 2 CTAs/SM. Warp owns 16 q-rows (fm=1). Q frags in registers; P converted
// c-frag -> a-frag via warp shuffles (no P smem, no syncwarp).
// One barrier per kv-iteration.
// ---------------------------------------------------------------------------
#define QSTR 68
#define KSTR 68
#define VSTR 72
#define K_TILE (64 * KSTR)
#define V_TILE (64 * VSTR)
#define ATT_SMEM ((128 * QSTR + 2 * K_TILE + 2 * V_TILE) * 4)
#define QK_SCALE 0.1803368801111364f    // 0.125 * log2(e)

__global__ __launch_bounds__(256, 2) void attn_tf32(
    const float* __restrict__ Qm, const float* __restrict__ Km,
    const float* __restrict__ Vm, float* __restrict__ Ctx)
{
    extern __shared__ float sm[];
    float* Qs = sm;                          // [128][QSTR]
    float* Ks = Qs + 128 * QSTR;             // [2][64][KSTR]
    float* Vs = Ks + 2 * K_TILE;             // [2][64][VSTR]

    const int tid  = threadIdx.x;
    const int warp = tid >> 5, lane = tid & 31;
    const int r = lane >> 2, c = lane & 3;
    const int wr = warp * 16;
    const int qb = blockIdx.x, h = blockIdx.y;
    const int cb = h * DK;

    // stage Q (128 x 64) + K/V tile 0 in one group
    {
        const uint32_t qdst = smem_u32(Qs);
#pragma unroll
        for (int i = 0; i < 8; i++) {
            int id = tid + 256 * i;
            int row = id >> 4, ch = id & 15;
            CP_ASYNC16(qdst + (uint32_t)(row * QSTR + ch * 4) * 4u,
                       Qm + (size_t)(qb * 128 + row) * D_MODEL + cb + ch * 4);
        }
        const uint32_t kdst = smem_u32(Ks);
        const uint32_t vdst = smem_u32(Vs);
#pragma unroll
        for (int i = 0; i < 4; i++) {
            int id = tid + 256 * i;
            int row = id >> 4, ch = id & 15;
            size_t g = (size_t)row * D_MODEL + cb + ch * 4;
            CP_ASYNC16(kdst + (uint32_t)(row * KSTR + ch * 4) * 4u, Km + g);
            CP_ASYNC16(vdst + (uint32_t)(row * VSTR + ch * 4) * 4u, Vm + g);
        }
        CP_COMMIT();
        CP_WAIT(0);
        __syncthreads();
    }

    // Q frags to registers (pre-scaled by 1/8 * log2(e))
    uint32_t qf[8][4];
#pragma unroll
    for (int ks = 0; ks < 8; ks++) {
        const float* p = Qs + (wr + r) * QSTR + ks * 8 + c;
        qf[ks][0] = f2u(p[0] * QK_SCALE);
        qf[ks][1] = f2u(p[8 * QSTR] * QK_SCALE);
        qf[ks][2] = f2u(p[4] * QK_SCALE);
        qf[ks][3] = f2u(p[8 * QSTR + 4] * QK_SCALE);
    }

    float mrow[2] = {-1e30f, -1e30f};
    float lrow[2] = {0.f, 0.f};
    float acc[8][4];
#pragma unroll
    for (int j = 0; j < 8; j++)
#pragma unroll
        for (int k = 0; k < 4; k++) acc[j][k] = 0.f;

    const uint32_t kdst = smem_u32(Ks);
    const uint32_t vdst = smem_u32(Vs);
    const int src1 = (lane & 0x1C) | (c >> 1);
    const int src2 = src1 + 2;
    const bool odd = (c & 1);

    for (int kt = 0; kt < S_LEN / 64; kt++) {
        const int buf = kt & 1;

        // prefetch next tile AFTER the barrier from the previous iteration
        // (at loop top all warps have finished reading buf^1)
        if (kt + 1 < S_LEN / 64) {
            const int nb = buf ^ 1;
#pragma unroll
            for (int i = 0; i < 4; i++) {
                int id = tid + 256 * i;
                int row = id >> 4, ch = id & 15;
                size_t g = (size_t)((kt + 1) * 64 + row) * D_MODEL + cb + ch * 4;
                CP_ASYNC16(kdst + (uint32_t)(nb * K_TILE + row * KSTR + ch * 4) * 4u, Km + g);
                CP_ASYNC16(vdst + (uint32_t)(nb * V_TILE + row * VSTR + ch * 4) * 4u, Vm + g);
            }
        }
        CP_COMMIT();

        // ---- S = Q @ K^T : m16 x n64 x k64 ----
        float s[8][4];
#pragma unroll
        for (int j = 0; j < 8; j++)
#pragma unroll
            for (int k = 0; k < 4; k++) s[j][k] = 0.f;

        const float* Kb = Ks + buf * K_TILE;
#pragma unroll
        for (int ks = 0; ks < 8; ks++) {
#pragma unroll
            for (int fn = 0; fn < 8; fn++) {
                const float* kp = Kb + (fn * 8 + r) * KSTR + ks * 8 + c;
                mma_tf32(s[fn], qf[ks], f2u(kp[0]), f2u(kp[4]));
            }
        }

        // ---- online softmax (rows wr+r, wr+r+8; quad-replicated) ----
        float mx0 = -1e30f, mx1 = -1e30f;
#pragma unroll
        for (int fn = 0; fn < 8; fn++) {
            mx0 = fmaxf(mx0, fmaxf(s[fn][0], s[fn][1]));
            mx1 = fmaxf(mx1, fmaxf(s[fn][2], s[fn][3]));
        }
        mx0 = fmaxf(mx0, __shfl_xor_sync(0xffffffffu, mx0, 1));
        mx0 = fmaxf(mx0, __shfl_xor_sync(0xffffffffu, mx0, 2));
        mx1 = fmaxf(mx1, __shfl_xor_sync(0xffffffffu, mx1, 1));
        mx1 = fmaxf(mx1, __shfl_xor_sync(0xffffffffu, mx1, 2));

        const float mn0 = fmaxf(mrow[0], mx0);
        const float mn1 = fmaxf(mrow[1], mx1);
        const float sc0 = exp2p(mrow[0] - mn0);
        const float sc1 = exp2p(mrow[1] - mn1);
        float ls0 = 0.f, ls1 = 0.f;
#pragma unroll
        for (int fn = 0; fn < 8; fn++) {
            s[fn][0] = exp2p(s[fn][0] - mn0);
            s[fn][1] = exp2p(s[fn][1] - mn0);
            s[fn][2] = exp2p(s[fn][2] - mn1);
            s[fn][3] = exp2p(s[fn][3] - mn1);
            ls0 += s[fn][0] + s[fn][1];
            ls1 += s[fn][2] + s[fn][3];
        }
        ls0 += __shfl_xor_sync(0xffffffffu, ls0, 1);
        ls0 += __shfl_xor_sync(0xffffffffu, ls0, 2);
        ls1 += __shfl_xor_sync(0xffffffffu, ls1, 1);
        ls1 += __shfl_xor_sync(0xffffffffu, ls1, 2);

        lrow[0] = lrow[0] * sc0 + ls0;
        lrow[1] = lrow[1] * sc1 + ls1;
        mrow[0] = mn0; mrow[1] = mn1;

#pragma unroll
        for (int fn = 0; fn < 8; fn++) {
            acc[fn][0] *= sc0; acc[fn][1] *= sc0;
            acc[fn][2] *= sc1; acc[fn][3] *= sc1;
        }

        // ---- O += P @ V : c-frag -> a-frag via shuffles, then mma ----
        const float* Vb = Vs + buf * V_TILE;
#pragma unroll
        for (int ks = 0; ks < 8; ks++) {
            float x0 = __shfl_sync(0xffffffffu, s[ks][0], src1);
            float x1 = __shfl_sync(0xffffffffu, s[ks][1], src1);
            float x2 = __shfl_sync(0xffffffffu, s[ks][2], src1);
            float x3 = __shfl_sync(0xffffffffu, s[ks][3], src1);
            float y0 = __shfl_sync(0xffffffffu, s[ks][0], src2);
            float y1 = __shfl_sync(0xffffffffu, s[ks][1], src2);
            float y2 = __shfl_sync(0xffffffffu, s[ks][2], src2);
            float y3 = __shfl_sync(0xffffffffu, s[ks][3], src2);
            uint32_t pa[4];
            pa[0] = f2u(odd ? x1 : x0);
            pa[1] = f2u(odd ? x3 : x2);
            pa[2] = f2u(odd ? y1 : y0);
            pa[3] = f2u(odd ? y3 : y2);
#pragma unroll
            for (int fn = 0; fn < 8; fn++) {
                const float* vp = Vb + (ks * 8 + c) * VSTR + fn * 8 + r;
                mma_tf32(acc[fn], pa, f2u(vp[0]), f2u(vp[4 * VSTR]));
            }
        }
        __syncthreads();   // all warps done with buf before next prefetch
    }

    // epilogue: normalize + store
    const float inv0 = 1.f / lrow[0];
    const float inv1 = 1.f / lrow[1];
    const int row0 = qb * 128 + wr + r;
    const int row1 = row0 + 8;
#pragma unroll
    for (int fn = 0; fn < 8; fn++) {
        const int col = cb + fn * 8 + 2 * c;
        *(float2*)&Ctx[(size_t)row0 * D_MODEL + col] =
            make_float2(acc[fn][0] * inv0, acc[fn][1] * inv0);
        *(float2*)&Ctx[(size_t)row1 * D_MODEL + col] =
            make_float2(acc[fn][2] * inv1, acc[fn][3] * inv1);
    }
}

// ---------------------------------------------------------------------------
extern "C" void kernel_launch(void* const* d_in, const int* in_sizes, int n_in,
                              void* d_out, int out_size)
{
    const float* x    = (const float*)d_in[0];
    const float* Wq   = (const float*)d_in[1];
    const float* bq   = (const float*)d_in[2];
    const float* Wk   = (const float*)d_in[3];
    const float* bk   = (const float*)d_in[4];
    const float* Wv   = (const float*)d_in[5];
    const float* bv   = (const float*)d_in[6];
    const float* Wo   = (const float*)d_in[7];
    const float* bo   = (const float*)d_in[8];
    const float* ln1a = (const float*)d_in[9];
    const float* ln1b = (const float*)d_in[10];
    const float* W1   = (const float*)d_in[11];
    const float* b1   = (const float*)d_in[12];
    const float* W2   = (const float*)d_in[13];
    const float* b2   = (const float*)d_in[14];
    const float* ln2a = (const float*)d_in[15];
    const float* ln2b = (const float*)d_in[16];
    float* out = (float*)d_out;

    float *h1, *Qm, *Km, *Vm, *ctx, *x1, *h2, *f1, *W3, *b3;
    cudaGetSymbolAddress((void**)&h1,  g_h1);
    cudaGetSymbolAddress((void**)&Qm,  g_Q);
    cudaGetSymbolAddress((void**)&Km,  g_K);
    cudaGetSymbolAddress((void**)&Vm,  g_V);
    cudaGetSymbolAddress((void**)&ctx, g_ctx);
    cudaGetSymbolAddress((void**)&x1,  g_x1);
    cudaGetSymbolAddress((void**)&h2,  g_h2);
    cudaGetSymbolAddress((void**)&f1,  g_f1);
    cudaGetSymbolAddress((void**)&W3,  g_W3);
    cudaGetSymbolAddress((void**)&b3,  g_b3);

    cudaFuncSetAttribute(mm_tf32<false, false>,
                         cudaFuncAttributeMaxDynamicSharedMemorySize, MM_SMEM);
    cudaFuncSetAttribute(mm_tf32<false, true>,
                         cudaFuncAttributeMaxDynamicSharedMemorySize, MM_SMEM);
    cudaFuncSetAttribute(mm_tf32<true, false>,
                         cudaFuncAttributeMaxDynamicSharedMemorySize, MM_SMEM);
    cudaFuncSetAttribute(attn_tf32,
                         cudaFuncAttributeMaxDynamicSharedMemorySize, ATT_SMEM);

    concat3<<<(D_MODEL * QKV_N) / 256, 256>>>(Wq, Wk, Wv, bq, bk, bv, W3, b3);

    const dim3 gQKV (QKV_N  / 128, S_LEN / 128);     // (24, 32)
    const dim3 gSmall(D_MODEL / 128, S_LEN / 128);   // (8, 32)
    const dim3 gFF1 (D_FF   / 128, S_LEN / 128);     // (32, 32)

    // residual 1
    ln_kernel<<<S_LEN, 256>>>(x, ln1a, ln1b, h1);
    mm_tf32<false, false><<<gQKV, 256, MM_SMEM>>>(h1, W3, b3, nullptr,
                                                  Qm, Km, Vm, S_LEN, QKV_N, D_MODEL);
    attn_tf32<<<dim3(S_LEN / 128, NUM_HEADS), 256, ATT_SMEM>>>(Qm, Km, Vm, ctx);
    mm_tf32<false, true><<<gSmall, 256, MM_SMEM>>>(ctx, Wo, bo, x,
                                                   x1, nullptr, nullptr, S_LEN, D_MODEL, D_MODEL);

    // residual 2
    ln_kernel<<<S_LEN, 256>>>(x1, ln2a, ln2b, h2);
    mm_tf32<true,  false><<<gFF1, 256, MM_SMEM>>>(h2, W1, b1, nullptr,
                                                  f1, nullptr, nullptr, S_LEN, D_FF, D_MODEL);
    mm_tf32<false, true><<<gSmall, 256, MM_SMEM>>>(f1, W2, b2, x1,
                                                   out, nullptr, nullptr, S_LEN, D_MODEL, D_FF);
}

// round 7
// speedup vs baseline: 1.6927x; 1.1128x over previous
#include <cuda_runtime.h>
#include <cuda_bf16.h>
#include <math.h>
#include <stdint.h>

// ---------------------------------------------------------------------------
// Encoder layer: B=1, S=4096, D=1024, H=16, dk=64, F=4096, fp32 in/out.
// tf32 mma.sync everywhere. R7: attention fm=2 (32 q-rows/warp), 128-thread
// CTAs, MUFU ex2 softmax, corrected cp.async wait discipline.
// ---------------------------------------------------------------------------

#define S_LEN 4096
#define D_MODEL 1024
#define D_FF 4096
#define NUM_HEADS 16
#define DK 64
#define QKV_N 3072

__device__ float g_h1[S_LEN * D_MODEL];
__device__ float g_Q [S_LEN * D_MODEL];
__device__ float g_K [S_LEN * D_MODEL];
__device__ float g_V [S_LEN * D_MODEL];
__device__ float g_ctx[S_LEN * D_MODEL];
__device__ float g_x1[S_LEN * D_MODEL];
__device__ float g_h2[S_LEN * D_MODEL];
__device__ float g_f1[S_LEN * D_FF];
__device__ float g_W3[D_MODEL * QKV_N];
__device__ float g_b3[QKV_N];

// ---------------------------------------------------------------------------
__device__ __forceinline__ void mma_tf32(float (&d)[4],
    const uint32_t (&a)[4], uint32_t b0, uint32_t b1)
{
    asm volatile(
        "mma.sync.aligned.m16n8k8.row.col.f32.tf32.tf32.f32 "
        "{%0,%1,%2,%3}, {%4,%5,%6,%7}, {%8,%9}, {%0,%1,%2,%3};\n"
        : "+f"(d[0]), "+f"(d[1]), "+f"(d[2]), "+f"(d[3])
        : "r"(a[0]), "r"(a[1]), "r"(a[2]), "r"(a[3]), "r"(b0), "r"(b1));
}
__device__ __forceinline__ uint32_t f2u(float x) { return __float_as_uint(x); }
__device__ __forceinline__ uint32_t smem_u32(const void* p) {
    return (uint32_t)__cvta_generic_to_shared(p);
}
#define CP_ASYNC16(dst, src) \
    asm volatile("cp.async.cg.shared.global [%0], [%1], 16;\n" :: "r"(dst), "l"(src))
#define CP_COMMIT() asm volatile("cp.async.commit_group;\n")
#define CP_WAIT(n)  asm volatile("cp.async.wait_group %0;\n" :: "n"(n))

// 2^x on the MUFU pipe (1 issue slot; accurate to ~2 ulp; underflows to 0)
__device__ __forceinline__ float ex2(float x) {
    float y;
    asm("ex2.approx.f32 %0, %1;" : "=f"(y) : "f"(x));
    return y;
}

// ---------------------------------------------------------------------------
// Concat Wq|Wk|Wv -> W3 [1024, 3072], bq|bk|bv -> b3 [3072]
// ---------------------------------------------------------------------------
__global__ __launch_bounds__(256) void concat3(
    const float* __restrict__ Wq, const float* __restrict__ Wk,
    const float* __restrict__ Wv, const float* __restrict__ bq,
    const float* __restrict__ bk, const float* __restrict__ bv,
    float* __restrict__ W3, float* __restrict__ b3)
{
    const int idx = blockIdx.x * 256 + threadIdx.x;
    const int k = idx / QKV_N, n = idx % QKV_N;
    const int sel = n >> 10, col = n & 1023;
    const float* W = sel == 0 ? Wq : (sel == 1 ? Wk : Wv);
    W3[idx] = W[k * D_MODEL + col];
    if (idx < QKV_N) {
        const float* b = sel == 0 ? bq : (sel == 1 ? bk : bv);
        b3[idx] = b[col];
    }
}

// ---------------------------------------------------------------------------
// LayerNorm (unbiased var ddof=1, denom = sqrt(var)+eps)
// ---------------------------------------------------------------------------
__global__ __launch_bounds__(256) void ln_kernel(
    const float* __restrict__ x, const float* __restrict__ alpha,
    const float* __restrict__ beta, float* __restrict__ y)
{
    const int row = blockIdx.x;
    const float4* xr = (const float4*)(x + (size_t)row * D_MODEL);
    float4* yr = (float4*)(y + (size_t)row * D_MODEL);
    const int tid = threadIdx.x;

    float4 xl = xr[tid];
    float s = xl.x + xl.y + xl.z + xl.w;

    __shared__ float sh[8];
#pragma unroll
    for (int o = 16; o > 0; o >>= 1) s += __shfl_xor_sync(0xffffffffu, s, o);
    if ((tid & 31) == 0) sh[tid >> 5] = s;
    __syncthreads();
    float mu = 0.f;
#pragma unroll
    for (int i = 0; i < 8; i++) mu += sh[i];
    mu *= (1.0f / D_MODEL);
    __syncthreads();

    float dx = xl.x - mu, dy = xl.y - mu, dz = xl.z - mu, dw = xl.w - mu;
    float v = dx * dx + dy * dy + dz * dz + dw * dw;
#pragma unroll
    for (int o = 16; o > 0; o >>= 1) v += __shfl_xor_sync(0xffffffffu, v, o);
    if ((tid & 31) == 0) sh[tid >> 5] = v;
    __syncthreads();
    float var = 0.f;
#pragma unroll
    for (int i = 0; i < 8; i++) var += sh[i];
    var *= (1.0f / (D_MODEL - 1));

    const float a = alpha[0], b = beta[0];
    const float inv = a / (sqrtf(var) + 1e-6f);
    float4 o;
    o.x = dx * inv + b; o.y = dy * inv + b;
    o.z = dz * inv + b; o.w = dw * inv + b;
    yr[tid] = o;
}

// ---------------------------------------------------------------------------
// TF32 GEMM: C = A[M,K] @ W[K,N] + bias (+relu) (+residual)
// BM=128 BN=128 BK=32, 256 threads, 3-stage cp.async, 1 barrier/k-tile,
// 2 CTAs/SM. If C1 != nullptr: N=3072 split into three [M,1024] outputs.
// ---------------------------------------------------------------------------
#define ASTR 36
#define BSTR 136
#define A_TILE (128 * ASTR)
#define B_TILE (32 * BSTR)
#define STG_F  (A_TILE + B_TILE)
#define MM_SMEM (3 * STG_F * 4)

template<bool RELU, bool RES>
__global__ __launch_bounds__(256, 2) void mm_tf32(
    const float* __restrict__ A, const float* __restrict__ W,
    const float* __restrict__ bias, const float* __restrict__ Rsd,
    float* __restrict__ C0, float* __restrict__ C1, float* __restrict__ C2,
    int M, int N, int K)
{
    extern __shared__ float smg[];

    const int tid  = threadIdx.x;
    const int warp = tid >> 5, lane = tid & 31;
    const int r = lane >> 2, c = lane & 3;
    const int wm = (warp >> 2) * 64, wn = (warp & 3) * 32;
    const int m0 = blockIdx.y * 128, n0 = blockIdx.x * 128;

    const uint32_t s0 = smem_u32(smg);

    float acc[4][4][4];
#pragma unroll
    for (int i = 0; i < 4; i++)
#pragma unroll
        for (int j = 0; j < 4; j++)
#pragma unroll
            for (int k = 0; k < 4; k++) acc[i][j][k] = 0.f;

    const int NK = K >> 5;

    auto load_tile = [&](int kt, int st) {
        const uint32_t ab = s0 + (uint32_t)(st * STG_F) * 4u;
        const uint32_t bb = ab + (uint32_t)A_TILE * 4u;
#pragma unroll
        for (int i = 0; i < 4; i++) {
            const int id = tid + 256 * i;
            const int ar = id >> 3, akc = id & 7;
            CP_ASYNC16(ab + (uint32_t)(ar * ASTR + akc * 4) * 4u,
                       A + (size_t)(m0 + ar) * K + kt * 32 + akc * 4);
            const int br = id >> 5, bnc = id & 31;
            CP_ASYNC16(bb + (uint32_t)(br * BSTR + bnc * 4) * 4u,
                       W + (size_t)(kt * 32 + br) * N + n0 + bnc * 4);
        }
    };

    load_tile(0, 0);
    CP_COMMIT();
    load_tile(1, 1);
    CP_COMMIT();

    for (int kt = 0; kt < NK; kt++) {
        const int st = kt - (kt / 3) * 3;
        CP_WAIT(1);
        __syncthreads();
        if (kt + 2 < NK) {
            const int s2 = (kt + 2) - ((kt + 2) / 3) * 3;
            load_tile(kt + 2, s2);
        }
        CP_COMMIT();

        const float* Ab = smg + st * STG_F;
        const float* Bb = Ab + A_TILE;
#pragma unroll
        for (int ks = 0; ks < 4; ks++) {
            uint32_t a[4][4], b[4][2];
#pragma unroll
            for (int fm = 0; fm < 4; fm++) {
                const float* p = Ab + (wm + fm * 16 + r) * ASTR + ks * 8 + c;
                a[fm][0] = f2u(p[0]);
                a[fm][1] = f2u(p[8 * ASTR]);
                a[fm][2] = f2u(p[4]);
                a[fm][3] = f2u(p[8 * ASTR + 4]);
            }
#pragma unroll
            for (int fn = 0; fn < 4; fn++) {
                const float* q = Bb + (ks * 8 + c) * BSTR + wn + fn * 8 + r;
                b[fn][0] = f2u(q[0]);
                b[fn][1] = f2u(q[4 * BSTR]);
            }
#pragma unroll
            for (int fm = 0; fm < 4; fm++)
#pragma unroll
                for (int fn = 0; fn < 4; fn++)
                    mma_tf32(acc[fm][fn], a[fm], b[fn][0], b[fn][1]);
        }
    }

    // output select (QKV split or single)
    float* Cc;
    int nl0, ldc;
    if (C1 != nullptr) {
        const int sel = n0 >> 10;
        Cc  = sel == 0 ? C0 : (sel == 1 ? C1 : C2);
        nl0 = n0 & 1023;
        ldc = 1024;
    } else {
        Cc = C0; nl0 = n0; ldc = N;
    }

#pragma unroll
    for (int fm = 0; fm < 4; fm++) {
        const int row0 = m0 + wm + fm * 16 + r;
        const int row1 = row0 + 8;
#pragma unroll
        for (int fn = 0; fn < 4; fn++) {
            const int colg = n0 + wn + fn * 8 + 2 * c;
            const int col  = nl0 + wn + fn * 8 + 2 * c;
            float2 bi = *(const float2*)&bias[colg];
            float v0 = acc[fm][fn][0] + bi.x;
            float v1 = acc[fm][fn][1] + bi.y;
            float v2 = acc[fm][fn][2] + bi.x;
            float v3 = acc[fm][fn][3] + bi.y;
            if (RELU) {
                v0 = fmaxf(v0, 0.f); v1 = fmaxf(v1, 0.f);
                v2 = fmaxf(v2, 0.f); v3 = fmaxf(v3, 0.f);
            }
            if (RES) {
                float2 r0 = *(const float2*)&Rsd[(size_t)row0 * ldc + col];
                float2 r1 = *(const float2*)&Rsd[(size_t)row1 * ldc + col];
                v0 += r0.x; v1 += r0.y; v2 += r1.x; v3 += r1.y;
            }
            *(float2*)&Cc[(size_t)row0 * ldc + col] = make_float2(v0, v1);
            *(float2*)&Cc[(size_t)row1 * ldc + col] = make_float2(v2, v3);
        }
    }
}

// ---------------------------------------------------------------------------
// Flash attention, tf32 mma.sync. grid = (S/128, H), 128 threads (4 warps),
// 2 CTAs/SM. Warp owns 32 q-rows (fm=2): K/V b-frags amortized over 2 mma.
// MUFU ex2 softmax. One barrier + one wait_group(0) per kv-iteration:
//   wait(0) -> sync -> prefetch nb -> compute buf.
// ---------------------------------------------------------------------------
#define QSTR 68
#define KSTR 68
#define VSTR 72
#define K_TILE (64 * KSTR)
#define V_TILE (64 * VSTR)
#define ATT_SMEM ((128 * QSTR + 2 * K_TILE + 2 * V_TILE) * 4)
#define QK_SCALE 0.1803368801111364f    // 0.125 * log2(e)

__global__ __launch_bounds__(128, 2) void attn_tf32(
    const float* __restrict__ Qm, const float* __restrict__ Km,
    const float* __restrict__ Vm, float* __restrict__ Ctx)
{
    extern __shared__ float sm[];
    float* Qs = sm;                          // [128][QSTR]
    float* Ks = Qs + 128 * QSTR;             // [2][64][KSTR]
    float* Vs = Ks + 2 * K_TILE;             // [2][64][VSTR]

    const int tid  = threadIdx.x;
    const int warp = tid >> 5, lane = tid & 31;
    const int r = lane >> 2, c = lane & 3;
    const int wr = warp * 32;
    const int qb = blockIdx.x, h = blockIdx.y;
    const int cb = h * DK;

    const uint32_t qdst = smem_u32(Qs);
    const uint32_t kdst = smem_u32(Ks);
    const uint32_t vdst = smem_u32(Vs);

    // stage Q (128x64) + K/V tile 0
#pragma unroll
    for (int i = 0; i < 16; i++) {
        int id = tid + 128 * i;
        int row = id >> 4, ch = id & 15;
        CP_ASYNC16(qdst + (uint32_t)(row * QSTR + ch * 4) * 4u,
                   Qm + (size_t)(qb * 128 + row) * D_MODEL + cb + ch * 4);
    }
#pragma unroll
    for (int i = 0; i < 8; i++) {
        int id = tid + 128 * i;
        int row = id >> 4, ch = id & 15;
        size_t g = (size_t)row * D_MODEL + cb + ch * 4;
        CP_ASYNC16(kdst + (uint32_t)(row * KSTR + ch * 4) * 4u, Km + g);
        CP_ASYNC16(vdst + (uint32_t)(row * VSTR + ch * 4) * 4u, Vm + g);
    }
    CP_COMMIT();
    CP_WAIT(0);
    __syncthreads();

    // Q frags to registers (pre-scaled by 1/8 * log2(e))
    uint32_t qf[2][8][4];
#pragma unroll
    for (int fm = 0; fm < 2; fm++)
#pragma unroll
        for (int ks = 0; ks < 8; ks++) {
            const float* p = Qs + (wr + fm * 16 + r) * QSTR + ks * 8 + c;
            qf[fm][ks][0] = f2u(p[0] * QK_SCALE);
            qf[fm][ks][1] = f2u(p[8 * QSTR] * QK_SCALE);
            qf[fm][ks][2] = f2u(p[4] * QK_SCALE);
            qf[fm][ks][3] = f2u(p[8 * QSTR + 4] * QK_SCALE);
        }

    float mrow[2][2] = {{-1e30f, -1e30f}, {-1e30f, -1e30f}};
    float lrow[2][2] = {{0.f, 0.f}, {0.f, 0.f}};
    float acc[2][8][4];
#pragma unroll
    for (int i = 0; i < 2; i++)
#pragma unroll
        for (int j = 0; j < 8; j++)
#pragma unroll
            for (int k = 0; k < 4; k++) acc[i][j][k] = 0.f;

    const int src1 = (lane & 0x1C) | (c >> 1);
    const int src2 = src1 + 2;
    const bool odd = (c & 1);

    for (int kt = 0; kt < S_LEN / 64; kt++) {
        const int buf = kt & 1;

        if (kt > 0) {
            CP_WAIT(0);        // tile kt (committed last iter) fully arrived
            __syncthreads();   // ...for ALL threads; prev buf reads finished
        }
        if (kt + 1 < S_LEN / 64) {
            const int nb = buf ^ 1;
#pragma unroll
            for (int i = 0; i < 8; i++) {
                int id = tid + 128 * i;
                int row = id >> 4, ch = id & 15;
                size_t g = (size_t)((kt + 1) * 64 + row) * D_MODEL + cb + ch * 4;
                CP_ASYNC16(kdst + (uint32_t)(nb * K_TILE + row * KSTR + ch * 4) * 4u, Km + g);
                CP_ASYNC16(vdst + (uint32_t)(nb * V_TILE + row * VSTR + ch * 4) * 4u, Vm + g);
            }
            CP_COMMIT();
        }

        // ---- S = Q @ K^T : m32 x n64 x k64 ----
        float s[2][8][4];
#pragma unroll
        for (int i = 0; i < 2; i++)
#pragma unroll
            for (int j = 0; j < 8; j++)
#pragma unroll
                for (int k = 0; k < 4; k++) s[i][j][k] = 0.f;

        const float* Kb = Ks + buf * K_TILE;
#pragma unroll
        for (int ks = 0; ks < 8; ks++) {
#pragma unroll
            for (int fn = 0; fn < 8; fn++) {
                const float* kp = Kb + (fn * 8 + r) * KSTR + ks * 8 + c;
                const uint32_t b0 = f2u(kp[0]);
                const uint32_t b1 = f2u(kp[4]);
                mma_tf32(s[0][fn], qf[0][ks], b0, b1);
                mma_tf32(s[1][fn], qf[1][ks], b0, b1);
            }
        }

        // ---- online softmax (MUFU ex2), rows wr+fm*16+{r, r+8} ----
#pragma unroll
        for (int fm = 0; fm < 2; fm++) {
            float mx0 = -1e30f, mx1 = -1e30f;
#pragma unroll
            for (int fn = 0; fn < 8; fn++) {
                mx0 = fmaxf(mx0, fmaxf(s[fm][fn][0], s[fm][fn][1]));
                mx1 = fmaxf(mx1, fmaxf(s[fm][fn][2], s[fm][fn][3]));
            }
            mx0 = fmaxf(mx0, __shfl_xor_sync(0xffffffffu, mx0, 1));
            mx0 = fmaxf(mx0, __shfl_xor_sync(0xffffffffu, mx0, 2));
            mx1 = fmaxf(mx1, __shfl_xor_sync(0xffffffffu, mx1, 1));
            mx1 = fmaxf(mx1, __shfl_xor_sync(0xffffffffu, mx1, 2));

            const float mn0 = fmaxf(mrow[fm][0], mx0);
            const float mn1 = fmaxf(mrow[fm][1], mx1);
            const float sc0 = ex2(mrow[fm][0] - mn0);
            const float sc1 = ex2(mrow[fm][1] - mn1);
            float ls0 = 0.f, ls1 = 0.f;
#pragma unroll
            for (int fn = 0; fn < 8; fn++) {
                s[fm][fn][0] = ex2(s[fm][fn][0] - mn0);
                s[fm][fn][1] = ex2(s[fm][fn][1] - mn0);
                s[fm][fn][2] = ex2(s[fm][fn][2] - mn1);
                s[fm][fn][3] = ex2(s[fm][fn][3] - mn1);
                ls0 += s[fm][fn][0] + s[fm][fn][1];
                ls1 += s[fm][fn][2] + s[fm][fn][3];
            }
            ls0 += __shfl_xor_sync(0xffffffffu, ls0, 1);
            ls0 += __shfl_xor_sync(0xffffffffu, ls0, 2);
            ls1 += __shfl_xor_sync(0xffffffffu, ls1, 1);
            ls1 += __shfl_xor_sync(0xffffffffu, ls1, 2);

            lrow[fm][0] = lrow[fm][0] * sc0 + ls0;
            lrow[fm][1] = lrow[fm][1] * sc1 + ls1;
            mrow[fm][0] = mn0; mrow[fm][1] = mn1;

#pragma unroll
            for (int fn = 0; fn < 8; fn++) {
                acc[fm][fn][0] *= sc0; acc[fm][fn][1] *= sc0;
                acc[fm][fn][2] *= sc1; acc[fm][fn][3] *= sc1;
            }
        }

        // ---- O += P @ V : c-frag -> a-frag via shuffles, then mma ----
        const float* Vb = Vs + buf * V_TILE;
#pragma unroll
        for (int ks = 0; ks < 8; ks++) {
            uint32_t pa[2][4];
#pragma unroll
            for (int fm = 0; fm < 2; fm++) {
                float x0 = __shfl_sync(0xffffffffu, s[fm][ks][0], src1);
                float x1 = __shfl_sync(0xffffffffu, s[fm][ks][1], src1);
                float x2 = __shfl_sync(0xffffffffu, s[fm][ks][2], src1);
                float x3 = __shfl_sync(0xffffffffu, s[fm][ks][3], src1);
                float y0 = __shfl_sync(0xffffffffu, s[fm][ks][0], src2);
                float y1 = __shfl_sync(0xffffffffu, s[fm][ks][1], src2);
                float y2 = __shfl_sync(0xffffffffu, s[fm][ks][2], src2);
                float y3 = __shfl_sync(0xffffffffu, s[fm][ks][3], src2);
                pa[fm][0] = f2u(odd ? x1 : x0);
                pa[fm][1] = f2u(odd ? x3 : x2);
                pa[fm][2] = f2u(odd ? y1 : y0);
                pa[fm][3] = f2u(odd ? y3 : y2);
            }
#pragma unroll
            for (int fn = 0; fn < 8; fn++) {
                const float* vp = Vb + (ks * 8 + c) * VSTR + fn * 8 + r;
                const uint32_t b0 = f2u(vp[0]);
                const uint32_t b1 = f2u(vp[4 * VSTR]);
                mma_tf32(acc[0][fn], pa[0], b0, b1);
                mma_tf32(acc[1][fn], pa[1], b0, b1);
            }
        }
    }

    // epilogue: normalize + store
#pragma unroll
    for (int fm = 0; fm < 2; fm++) {
        const float inv0 = 1.f / lrow[fm][0];
        const float inv1 = 1.f / lrow[fm][1];
        const int row0 = qb * 128 + wr + fm * 16 + r;
        const int row1 = row0 + 8;
#pragma unroll
        for (int fn = 0; fn < 8; fn++) {
            const int col = cb + fn * 8 + 2 * c;
            *(float2*)&Ctx[(size_t)row0 * D_MODEL + col] =
                make_float2(acc[fm][fn][0] * inv0, acc[fm][fn][1] * inv0);
            *(float2*)&Ctx[(size_t)row1 * D_MODEL + col] =
                make_float2(acc[fm][fn][2] * inv1, acc[fm][fn][3] * inv1);
        }
    }
}

// ---------------------------------------------------------------------------
extern "C" void kernel_launch(void* const* d_in, const int* in_sizes, int n_in,
                              void* d_out, int out_size)
{
    const float* x    = (const float*)d_in[0];
    const float* Wq   = (const float*)d_in[1];
    const float* bq   = (const float*)d_in[2];
    const float* Wk   = (const float*)d_in[3];
    const float* bk   = (const float*)d_in[4];
    const float* Wv   = (const float*)d_in[5];
    const float* bv   = (const float*)d_in[6];
    const float* Wo   = (const float*)d_in[7];
    const float* bo   = (const float*)d_in[8];
    const float* ln1a = (const float*)d_in[9];
    const float* ln1b = (const float*)d_in[10];
    const float* W1   = (const float*)d_in[11];
    const float* b1   = (const float*)d_in[12];
    const float* W2   = (const float*)d_in[13];
    const float* b2   = (const float*)d_in[14];
    const float* ln2a = (const float*)d_in[15];
    const float* ln2b = (const float*)d_in[16];
    float* out = (float*)d_out;

    float *h1, *Qm, *Km, *Vm, *ctx, *x1, *h2, *f1, *W3, *b3;
    cudaGetSymbolAddress((void**)&h1,  g_h1);
    cudaGetSymbolAddress((void**)&Qm,  g_Q);
    cudaGetSymbolAddress((void**)&Km,  g_K);
    cudaGetSymbolAddress((void**)&Vm,  g_V);
    cudaGetSymbolAddress((void**)&ctx, g_ctx);
    cudaGetSymbolAddress((void**)&x1,  g_x1);
    cudaGetSymbolAddress((void**)&h2,  g_h2);
    cudaGetSymbolAddress((void**)&f1,  g_f1);
    cudaGetSymbolAddress((void**)&W3,  g_W3);
    cudaGetSymbolAddress((void**)&b3,  g_b3);

    cudaFuncSetAttribute(mm_tf32<false, false>,
                         cudaFuncAttributeMaxDynamicSharedMemorySize, MM_SMEM);
    cudaFuncSetAttribute(mm_tf32<false, true>,
                         cudaFuncAttributeMaxDynamicSharedMemorySize, MM_SMEM);
    cudaFuncSetAttribute(mm_tf32<true, false>,
                         cudaFuncAttributeMaxDynamicSharedMemorySize, MM_SMEM);
    cudaFuncSetAttribute(attn_tf32,
                         cudaFuncAttributeMaxDynamicSharedMemorySize, ATT_SMEM);

    concat3<<<(D_MODEL * QKV_N) / 256, 256>>>(Wq, Wk, Wv, bq, bk, bv, W3, b3);

    const dim3 gQKV (QKV_N  / 128, S_LEN / 128);     // (24, 32)
    const dim3 gSmall(D_MODEL / 128, S_LEN / 128);   // (8, 32)
    const dim3 gFF1 (D_FF   / 128, S_LEN / 128);     // (32, 32)

    // residual 1
    ln_kernel<<<S_LEN, 256>>>(x, ln1a, ln1b, h1);
    mm_tf32<false, false><<<gQKV, 256, MM_SMEM>>>(h1, W3, b3, nullptr,
                                                  Qm, Km, Vm, S_LEN, QKV_N, D_MODEL);
    attn_tf32<<<dim3(S_LEN / 128, NUM_HEADS), 128, ATT_SMEM>>>(Qm, Km, Vm, ctx);
    mm_tf32<false, true><<<gSmall, 256, MM_SMEM>>>(ctx, Wo, bo, x,
                                                   x1, nullptr, nullptr, S_LEN, D_MODEL, D_MODEL);

    // residual 2
    ln_kernel<<<S_LEN, 256>>>(x1, ln2a, ln2b, h2);
    mm_tf32<true,  false><<<gFF1, 256, MM_SMEM>>>(h2, W1, b1, nullptr,
                                                  f1, nullptr, nullptr, S_LEN, D_FF, D_MODEL);
    mm_tf32<false, true><<<gSmall, 256, MM_SMEM>>>(f1, W2, b2, x1,
                                                   out, nullptr, nullptr, S_LEN, D_MODEL, D_FF);
}

// round 8
// speedup vs baseline: 2.1017x; 1.2416x over previous
#include <cuda_runtime.h>
#include <cuda_bf16.h>
#include <math.h>
#include <stdint.h>

// ---------------------------------------------------------------------------
// Encoder layer: B=1, S=4096, D=1024, H=16, dk=64, F=4096, fp32 in/out.
// GEMMs: tf32 mma.sync (fp32 accuracy path). Attention: bf16 m16n8k16 mma
// with FA2 c-frag->a-frag packing (zero shuffles), Q/K bf16 from GEMM
// epilogue, V transposed+converted to bf16 by a small kernel.
// ---------------------------------------------------------------------------

#define S_LEN 4096
#define D_MODEL 1024
#define D_FF 4096
#define NUM_HEADS 16
#define DK 64
#define QKV_N 3072

__device__ float g_h1[S_LEN * D_MODEL];
__device__ __nv_bfloat16 g_Qb[S_LEN * D_MODEL];
__device__ __nv_bfloat16 g_Kb[S_LEN * D_MODEL];
__device__ float g_V [S_LEN * D_MODEL];
__device__ __nv_bfloat16 g_Vt[D_MODEL * S_LEN];   // [dim][key]
__device__ float g_ctx[S_LEN * D_MODEL];
__device__ float g_x1[S_LEN * D_MODEL];
__device__ float g_h2[S_LEN * D_MODEL];
__device__ float g_f1[S_LEN * D_FF];
__device__ float g_W3[D_MODEL * QKV_N];
__device__ float g_b3[QKV_N];

// ---------------------------------------------------------------------------
__device__ __forceinline__ void mma_tf32(float (&d)[4],
    const uint32_t (&a)[4], uint32_t b0, uint32_t b1)
{
    asm volatile(
        "mma.sync.aligned.m16n8k8.row.col.f32.tf32.tf32.f32 "
        "{%0,%1,%2,%3}, {%4,%5,%6,%7}, {%8,%9}, {%0,%1,%2,%3};\n"
        : "+f"(d[0]), "+f"(d[1]), "+f"(d[2]), "+f"(d[3])
        : "r"(a[0]), "r"(a[1]), "r"(a[2]), "r"(a[3]), "r"(b0), "r"(b1));
}
__device__ __forceinline__ void mma_bf16(float (&d)[4],
    const uint32_t (&a)[4], uint32_t b0, uint32_t b1)
{
    asm volatile(
        "mma.sync.aligned.m16n8k16.row.col.f32.bf16.bf16.f32 "
        "{%0,%1,%2,%3}, {%4,%5,%6,%7}, {%8,%9}, {%0,%1,%2,%3};\n"
        : "+f"(d[0]), "+f"(d[1]), "+f"(d[2]), "+f"(d[3])
        : "r"(a[0]), "r"(a[1]), "r"(a[2]), "r"(a[3]), "r"(b0), "r"(b1));
}
__device__ __forceinline__ uint32_t f2u(float x) { return __float_as_uint(x); }
__device__ __forceinline__ uint32_t smem_u32(const void* p) {
    return (uint32_t)__cvta_generic_to_shared(p);
}
__device__ __forceinline__ uint32_t pack_bf16(float lo, float hi) {
    __nv_bfloat162 v = __floats2bfloat162_rn(lo, hi);   // .x = lo (low half)
    return *(uint32_t*)&v;
}
#define CP_ASYNC16(dst, src) \
    asm volatile("cp.async.cg.shared.global [%0], [%1], 16;\n" :: "r"(dst), "l"(src))
#define CP_COMMIT() asm volatile("cp.async.commit_group;\n")
#define CP_WAIT(n)  asm volatile("cp.async.wait_group %0;\n" :: "n"(n))

// 2^x on the MUFU pipe
__device__ __forceinline__ float ex2(float x) {
    float y;
    asm("ex2.approx.f32 %0, %1;" : "=f"(y) : "f"(x));
    return y;
}

// ---------------------------------------------------------------------------
// Concat Wq|Wk|Wv -> W3 [1024, 3072], bq|bk|bv -> b3 [3072]
// ---------------------------------------------------------------------------
__global__ __launch_bounds__(256) void concat3(
    const float* __restrict__ Wq, const float* __restrict__ Wk,
    const float* __restrict__ Wv, const float* __restrict__ bq,
    const float* __restrict__ bk, const float* __restrict__ bv,
    float* __restrict__ W3, float* __restrict__ b3)
{
    const int idx = blockIdx.x * 256 + threadIdx.x;
    const int k = idx / QKV_N, n = idx % QKV_N;
    const int sel = n >> 10, col = n & 1023;
    const float* W = sel == 0 ? Wq : (sel == 1 ? Wk : Wv);
    W3[idx] = W[k * D_MODEL + col];
    if (idx < QKV_N) {
        const float* b = sel == 0 ? bq : (sel == 1 ? bk : bv);
        b3[idx] = b[col];
    }
}

// ---------------------------------------------------------------------------
// V [S,1024] fp32 -> Vt [1024,S] bf16 (transpose + convert)
// ---------------------------------------------------------------------------
__global__ __launch_bounds__(256) void vtrans(
    const float* __restrict__ V, __nv_bfloat16* __restrict__ Vt)
{
    __shared__ float t[64][33];
    const int k0 = blockIdx.x * 64;   // key tile
    const int d0 = blockIdx.y * 32;   // dim tile
    const int x = threadIdx.x & 31;
    const int y = threadIdx.x >> 5;   // 0..7
#pragma unroll
    for (int i = 0; i < 64; i += 8)
        t[y + i][x] = V[(size_t)(k0 + y + i) * D_MODEL + d0 + x];
    __syncthreads();
    uint32_t* Vt32 = (uint32_t*)Vt;
#pragma unroll
    for (int p = 0; p < 4; p++) {
        const int d = y + 8 * p;              // dim within tile
        const int j = x;                      // u32 index: keys 2j, 2j+1
        uint32_t v = pack_bf16(t[2 * j][d], t[2 * j + 1][d]);
        Vt32[(size_t)(d0 + d) * (S_LEN / 2) + (k0 >> 1) + j] = v;
    }
}

// ---------------------------------------------------------------------------
// LayerNorm (unbiased var ddof=1, denom = sqrt(var)+eps)
// ---------------------------------------------------------------------------
__global__ __launch_bounds__(256) void ln_kernel(
    const float* __restrict__ x, const float* __restrict__ alpha,
    const float* __restrict__ beta, float* __restrict__ y)
{
    const int row = blockIdx.x;
    const float4* xr = (const float4*)(x + (size_t)row * D_MODEL);
    float4* yr = (float4*)(y + (size_t)row * D_MODEL);
    const int tid = threadIdx.x;

    float4 xl = xr[tid];
    float s = xl.x + xl.y + xl.z + xl.w;

    __shared__ float sh[8];
#pragma unroll
    for (int o = 16; o > 0; o >>= 1) s += __shfl_xor_sync(0xffffffffu, s, o);
    if ((tid & 31) == 0) sh[tid >> 5] = s;
    __syncthreads();
    float mu = 0.f;
#pragma unroll
    for (int i = 0; i < 8; i++) mu += sh[i];
    mu *= (1.0f / D_MODEL);
    __syncthreads();

    float dx = xl.x - mu, dy = xl.y - mu, dz = xl.z - mu, dw = xl.w - mu;
    float v = dx * dx + dy * dy + dz * dz + dw * dw;
#pragma unroll
    for (int o = 16; o > 0; o >>= 1) v += __shfl_xor_sync(0xffffffffu, v, o);
    if ((tid & 31) == 0) sh[tid >> 5] = v;
    __syncthreads();
    float var = 0.f;
#pragma unroll
    for (int i = 0; i < 8; i++) var += sh[i];
    var *= (1.0f / (D_MODEL - 1));

    const float a = alpha[0], b = beta[0];
    const float inv = a / (sqrtf(var) + 1e-6f);
    float4 o;
    o.x = dx * inv + b; o.y = dy * inv + b;
    o.z = dz * inv + b; o.w = dw * inv + b;
    yr[tid] = o;
}

// ---------------------------------------------------------------------------
// TF32 GEMM: C = A[M,K] @ W[K,N] + bias (+relu) (+residual)
// BM=128 BN=128 BK=32, 256 threads, 3-stage cp.async, 1 barrier/k-tile,
// 2 CTAs/SM. QKV mode (C1 != nullptr): Q,K outputs bf16; V output fp32.
// ---------------------------------------------------------------------------
#define ASTR 36
#define BSTR 136
#define A_TILE (128 * ASTR)
#define B_TILE (32 * BSTR)
#define STG_F  (A_TILE + B_TILE)
#define MM_SMEM (3 * STG_F * 4)

template<bool RELU, bool RES>
__global__ __launch_bounds__(256, 2) void mm_tf32(
    const float* __restrict__ A, const float* __restrict__ W,
    const float* __restrict__ bias, const float* __restrict__ Rsd,
    float* __restrict__ C0, float* __restrict__ C1, float* __restrict__ C2,
    int M, int N, int K)
{
    extern __shared__ float smg[];

    const int tid  = threadIdx.x;
    const int warp = tid >> 5, lane = tid & 31;
    const int r = lane >> 2, c = lane & 3;
    const int wm = (warp >> 2) * 64, wn = (warp & 3) * 32;
    const int m0 = blockIdx.y * 128, n0 = blockIdx.x * 128;

    const uint32_t s0 = smem_u32(smg);

    float acc[4][4][4];
#pragma unroll
    for (int i = 0; i < 4; i++)
#pragma unroll
        for (int j = 0; j < 4; j++)
#pragma unroll
            for (int k = 0; k < 4; k++) acc[i][j][k] = 0.f;

    const int NK = K >> 5;

    auto load_tile = [&](int kt, int st) {
        const uint32_t ab = s0 + (uint32_t)(st * STG_F) * 4u;
        const uint32_t bb = ab + (uint32_t)A_TILE * 4u;
#pragma unroll
        for (int i = 0; i < 4; i++) {
            const int id = tid + 256 * i;
            const int ar = id >> 3, akc = id & 7;
            CP_ASYNC16(ab + (uint32_t)(ar * ASTR + akc * 4) * 4u,
                       A + (size_t)(m0 + ar) * K + kt * 32 + akc * 4);
            const int br = id >> 5, bnc = id & 31;
            CP_ASYNC16(bb + (uint32_t)(br * BSTR + bnc * 4) * 4u,
                       W + (size_t)(kt * 32 + br) * N + n0 + bnc * 4);
        }
    };

    load_tile(0, 0);
    CP_COMMIT();
    load_tile(1, 1);
    CP_COMMIT();

    for (int kt = 0; kt < NK; kt++) {
        const int st = kt - (kt / 3) * 3;
        CP_WAIT(1);
        __syncthreads();
        if (kt + 2 < NK) {
            const int s2 = (kt + 2) - ((kt + 2) / 3) * 3;
            load_tile(kt + 2, s2);
        }
        CP_COMMIT();

        const float* Ab = smg + st * STG_F;
        const float* Bb = Ab + A_TILE;
#pragma unroll
        for (int ks = 0; ks < 4; ks++) {
            uint32_t a[4][4], b[4][2];
#pragma unroll
            for (int fm = 0; fm < 4; fm++) {
                const float* p = Ab + (wm + fm * 16 + r) * ASTR + ks * 8 + c;
                a[fm][0] = f2u(p[0]);
                a[fm][1] = f2u(p[8 * ASTR]);
                a[fm][2] = f2u(p[4]);
                a[fm][3] = f2u(p[8 * ASTR + 4]);
            }
#pragma unroll
            for (int fn = 0; fn < 4; fn++) {
                const float* q = Bb + (ks * 8 + c) * BSTR + wn + fn * 8 + r;
                b[fn][0] = f2u(q[0]);
                b[fn][1] = f2u(q[4 * BSTR]);
            }
#pragma unroll
            for (int fm = 0; fm < 4; fm++)
#pragma unroll
                for (int fn = 0; fn < 4; fn++)
                    mma_tf32(acc[fm][fn], a[fm], b[fn][0], b[fn][1]);
        }
    }

    if (C1 != nullptr) {
        // QKV mode: sel 0/1 -> bf16 Q/K; sel 2 -> fp32 V. ld = 1024.
        const int sel = n0 >> 10;
        const int nl0 = n0 & 1023;
        if (sel < 2) {
            __nv_bfloat16* Cb = (__nv_bfloat16*)(sel == 0 ? (void*)C0 : (void*)C1);
#pragma unroll
            for (int fm = 0; fm < 4; fm++) {
                const int row0 = m0 + wm + fm * 16 + r;
                const int row1 = row0 + 8;
#pragma unroll
                for (int fn = 0; fn < 4; fn++) {
                    const int colg = n0 + wn + fn * 8 + 2 * c;
                    const int col  = nl0 + wn + fn * 8 + 2 * c;
                    float2 bi = *(const float2*)&bias[colg];
                    uint32_t p0 = pack_bf16(acc[fm][fn][0] + bi.x, acc[fm][fn][1] + bi.y);
                    uint32_t p1 = pack_bf16(acc[fm][fn][2] + bi.x, acc[fm][fn][3] + bi.y);
                    *(uint32_t*)&Cb[(size_t)row0 * 1024 + col] = p0;
                    *(uint32_t*)&Cb[(size_t)row1 * 1024 + col] = p1;
                }
            }
        } else {
#pragma unroll
            for (int fm = 0; fm < 4; fm++) {
                const int row0 = m0 + wm + fm * 16 + r;
                const int row1 = row0 + 8;
#pragma unroll
                for (int fn = 0; fn < 4; fn++) {
                    const int colg = n0 + wn + fn * 8 + 2 * c;
                    const int col  = nl0 + wn + fn * 8 + 2 * c;
                    float2 bi = *(const float2*)&bias[colg];
                    *(float2*)&C2[(size_t)row0 * 1024 + col] =
                        make_float2(acc[fm][fn][0] + bi.x, acc[fm][fn][1] + bi.y);
                    *(float2*)&C2[(size_t)row1 * 1024 + col] =
                        make_float2(acc[fm][fn][2] + bi.x, acc[fm][fn][3] + bi.y);
                }
            }
        }
        return;
    }

#pragma unroll
    for (int fm = 0; fm < 4; fm++) {
        const int row0 = m0 + wm + fm * 16 + r;
        const int row1 = row0 + 8;
#pragma unroll
        for (int fn = 0; fn < 4; fn++) {
            const int col = n0 + wn + fn * 8 + 2 * c;
            float2 bi = *(const float2*)&bias[col];
            float v0 = acc[fm][fn][0] + bi.x;
            float v1 = acc[fm][fn][1] + bi.y;
            float v2 = acc[fm][fn][2] + bi.x;
            float v3 = acc[fm][fn][3] + bi.y;
            if (RELU) {
                v0 = fmaxf(v0, 0.f); v1 = fmaxf(v1, 0.f);
                v2 = fmaxf(v2, 0.f); v3 = fmaxf(v3, 0.f);
            }
            if (RES) {
                float2 r0 = *(const float2*)&Rsd[(size_t)row0 * N + col];
                float2 r1 = *(const float2*)&Rsd[(size_t)row1 * N + col];
                v0 += r0.x; v1 += r0.y; v2 += r1.x; v3 += r1.y;
            }
            *(float2*)&C0[(size_t)row0 * N + col] = make_float2(v0, v1);
            *(float2*)&C0[(size_t)row1 * N + col] = make_float2(v2, v3);
        }
    }
}

// ---------------------------------------------------------------------------
// Flash attention, bf16 m16n8k16 mma. grid = (S/128, H), 128 threads,
// 2 CTAs/SM. Warp owns 32 q-rows (fm=2). Softmax in raw score domain with
// the 0.125*log2e scale folded into the exp FMA. P packed c->a frag via
// cvt.rn.bf16x2 (zero shuffles). smem strides 36 u32: all LDS conflict-free.
// ---------------------------------------------------------------------------
#define ASTRU 36                           // u32 stride (64 bf16 + pad)
#define QTILE_U (128 * ASTRU)
#define KTILE_U (64 * ASTRU)
#define ATT_SMEM ((QTILE_U + 4 * KTILE_U) * 4)
#define QK_SCALE 0.1803368801111364f       // 0.125 * log2(e)

__global__ __launch_bounds__(128, 2) void attn_bf16(
    const __nv_bfloat16* __restrict__ Qm, const __nv_bfloat16* __restrict__ Km,
    const __nv_bfloat16* __restrict__ Vt, float* __restrict__ Ctx)
{
    extern __shared__ uint32_t su[];
    uint32_t* Qs = su;                     // [128][36]
    uint32_t* Ks = Qs + QTILE_U;           // [2][64][36]
    uint32_t* Vs = Ks + 2 * KTILE_U;       // [2][64][36]  (Vt tile: dim-major)

    const int tid  = threadIdx.x;
    const int warp = tid >> 5, lane = tid & 31;
    const int r = lane >> 2, c = lane & 3;
    const int wr = warp * 32;
    const int qb = blockIdx.x, h = blockIdx.y;
    const int cb = h * DK;

    const uint32_t qdst = smem_u32(Qs);
    const uint32_t kdst = smem_u32(Ks);
    const uint32_t vdst = smem_u32(Vs);

    // stage Q (128 rows x 64 dims bf16) + K/V tile 0
#pragma unroll
    for (int i = 0; i < 8; i++) {
        int id = tid + 128 * i;
        int row = id >> 3, ch = id & 7;
        CP_ASYNC16(qdst + (uint32_t)(row * ASTRU + ch * 4) * 4u,
                   Qm + (size_t)(qb * 128 + row) * D_MODEL + cb + ch * 8);
    }
#pragma unroll
    for (int i = 0; i < 4; i++) {
        int id = tid + 128 * i;
        int row = id >> 3, ch = id & 7;
        CP_ASYNC16(kdst + (uint32_t)(row * ASTRU + ch * 4) * 4u,
                   Km + (size_t)row * D_MODEL + cb + ch * 8);
        CP_ASYNC16(vdst + (uint32_t)(row * ASTRU + ch * 4) * 4u,
                   Vt + (size_t)(cb + row) * S_LEN + ch * 8);
    }
    CP_COMMIT();
    CP_WAIT(0);
    __syncthreads();

    // Q a-frags (bf16 pairs) cached in registers: 4 k16-blocks x 4 regs x 2 fm
    uint32_t qf[2][4][4];
#pragma unroll
    for (int fm = 0; fm < 2; fm++)
#pragma unroll
        for (int ks = 0; ks < 4; ks++) {
            const int row = wr + fm * 16 + r;
            qf[fm][ks][0] = Qs[row * ASTRU + 8 * ks + c];
            qf[fm][ks][1] = Qs[(row + 8) * ASTRU + 8 * ks + c];
            qf[fm][ks][2] = Qs[row * ASTRU + 8 * ks + c + 4];
            qf[fm][ks][3] = Qs[(row + 8) * ASTRU + 8 * ks + c + 4];
        }

    float mrow[2][2] = {{-1e30f, -1e30f}, {-1e30f, -1e30f}};
    float lrow[2][2] = {{0.f, 0.f}, {0.f, 0.f}};
    float acc[2][8][4];
#pragma unroll
    for (int i = 0; i < 2; i++)
#pragma unroll
        for (int j = 0; j < 8; j++)
#pragma unroll
            for (int k = 0; k < 4; k++) acc[i][j][k] = 0.f;

    for (int kt = 0; kt < S_LEN / 64; kt++) {
        const int buf = kt & 1;

        if (kt > 0) {
            CP_WAIT(0);
            __syncthreads();
        }
        if (kt + 1 < S_LEN / 64) {
            const int nb = buf ^ 1;
#pragma unroll
            for (int i = 0; i < 4; i++) {
                int id = tid + 128 * i;
                int row = id >> 3, ch = id & 7;
                CP_ASYNC16(kdst + (uint32_t)(nb * KTILE_U + row * ASTRU + ch * 4) * 4u,
                           Km + (size_t)((kt + 1) * 64 + row) * D_MODEL + cb + ch * 8);
                CP_ASYNC16(vdst + (uint32_t)(nb * KTILE_U + row * ASTRU + ch * 4) * 4u,
                           Vt + (size_t)(cb + row) * S_LEN + (kt + 1) * 64 + ch * 8);
            }
            CP_COMMIT();
        }

        // ---- S = Q @ K^T : m32 x n64 x k64 (4 k16 blocks) ----
        float s[2][8][4];
#pragma unroll
        for (int i = 0; i < 2; i++)
#pragma unroll
            for (int j = 0; j < 8; j++)
#pragma unroll
                for (int k = 0; k < 4; k++) s[i][j][k] = 0.f;

        const uint32_t* Kb = Ks + buf * KTILE_U;
#pragma unroll
        for (int ks = 0; ks < 4; ks++) {
#pragma unroll
            for (int fn = 0; fn < 8; fn++) {
                const uint32_t b0 = Kb[(8 * fn + r) * ASTRU + 8 * ks + c];
                const uint32_t b1 = Kb[(8 * fn + r) * ASTRU + 8 * ks + c + 4];
                mma_bf16(s[0][fn], qf[0][ks], b0, b1);
                mma_bf16(s[1][fn], qf[1][ks], b0, b1);
            }
        }

        // ---- online softmax (raw domain; scale folded into exp fma) ----
        uint32_t pa[2][4][4];
#pragma unroll
        for (int fm = 0; fm < 2; fm++) {
            float mx0 = -1e30f, mx1 = -1e30f;
#pragma unroll
            for (int fn = 0; fn < 8; fn++) {
                mx0 = fmaxf(mx0, fmaxf(s[fm][fn][0], s[fm][fn][1]));
                mx1 = fmaxf(mx1, fmaxf(s[fm][fn][2], s[fm][fn][3]));
            }
            mx0 = fmaxf(mx0, __shfl_xor_sync(0xffffffffu, mx0, 1));
            mx0 = fmaxf(mx0, __shfl_xor_sync(0xffffffffu, mx0, 2));
            mx1 = fmaxf(mx1, __shfl_xor_sync(0xffffffffu, mx1, 1));
            mx1 = fmaxf(mx1, __shfl_xor_sync(0xffffffffu, mx1, 2));

            const float mn0 = fmaxf(mrow[fm][0], mx0);
            const float mn1 = fmaxf(mrow[fm][1], mx1);
            const float emn0 = mn0 * QK_SCALE;
            const float emn1 = mn1 * QK_SCALE;
            const float sc0 = ex2(fmaf(mrow[fm][0], QK_SCALE, -emn0));
            const float sc1 = ex2(fmaf(mrow[fm][1], QK_SCALE, -emn1));
            float ls0 = 0.f, ls1 = 0.f;
#pragma unroll
            for (int fn = 0; fn < 8; fn++) {
                float e0 = ex2(fmaf(s[fm][fn][0], QK_SCALE, -emn0));
                float e1 = ex2(fmaf(s[fm][fn][1], QK_SCALE, -emn0));
                float e2 = ex2(fmaf(s[fm][fn][2], QK_SCALE, -emn1));
                float e3 = ex2(fmaf(s[fm][fn][3], QK_SCALE, -emn1));
                ls0 += e0 + e1;
                ls1 += e2 + e3;
                // c-frag -> m16n8k16 a-frag packing (FA2 identity)
                pa[fm][fn >> 1][(fn & 1) * 2 + 0] = pack_bf16(e0, e1);  // row g
                pa[fm][fn >> 1][(fn & 1) * 2 + 1] = pack_bf16(e2, e3);  // row g+8
            }
            ls0 += __shfl_xor_sync(0xffffffffu, ls0, 1);
            ls0 += __shfl_xor_sync(0xffffffffu, ls0, 2);
            ls1 += __shfl_xor_sync(0xffffffffu, ls1, 1);
            ls1 += __shfl_xor_sync(0xffffffffu, ls1, 2);

            lrow[fm][0] = lrow[fm][0] * sc0 + ls0;
            lrow[fm][1] = lrow[fm][1] * sc1 + ls1;
            mrow[fm][0] = mn0; mrow[fm][1] = mn1;

#pragma unroll
            for (int fn = 0; fn < 8; fn++) {
                acc[fm][fn][0] *= sc0; acc[fm][fn][1] *= sc0;
                acc[fm][fn][2] *= sc1; acc[fm][fn][3] *= sc1;
            }
        }

        // ---- O += P @ V : b-frags from dim-major Vt tile ----
        const uint32_t* Vb = Vs + buf * KTILE_U;
#pragma unroll
        for (int ks = 0; ks < 4; ks++) {
#pragma unroll
            for (int fn = 0; fn < 8; fn++) {
                const uint32_t b0 = Vb[(8 * fn + r) * ASTRU + 8 * ks + c];
                const uint32_t b1 = Vb[(8 * fn + r) * ASTRU + 8 * ks + c + 4];
                mma_bf16(acc[0][fn], pa[0][ks], b0, b1);
                mma_bf16(acc[1][fn], pa[1][ks], b0, b1);
            }
        }
    }

    // epilogue: normalize + store
#pragma unroll
    for (int fm = 0; fm < 2; fm++) {
        const float inv0 = 1.f / lrow[fm][0];
        const float inv1 = 1.f / lrow[fm][1];
        const int row0 = qb * 128 + wr + fm * 16 + r;
        const int row1 = row0 + 8;
#pragma unroll
        for (int fn = 0; fn < 8; fn++) {
            const int col = cb + fn * 8 + 2 * c;
            *(float2*)&Ctx[(size_t)row0 * D_MODEL + col] =
                make_float2(acc[fm][fn][0] * inv0, acc[fm][fn][1] * inv0);
            *(float2*)&Ctx[(size_t)row1 * D_MODEL + col] =
                make_float2(acc[fm][fn][2] * inv1, acc[fm][fn][3] * inv1);
        }
    }
}

// ---------------------------------------------------------------------------
extern "C" void kernel_launch(void* const* d_in, const int* in_sizes, int n_in,
                              void* d_out, int out_size)
{
    const float* x    = (const float*)d_in[0];
    const float* Wq   = (const float*)d_in[1];
    const float* bq   = (const float*)d_in[2];
    const float* Wk   = (const float*)d_in[3];
    const float* bk   = (const float*)d_in[4];
    const float* Wv   = (const float*)d_in[5];
    const float* bv   = (const float*)d_in[6];
    const float* Wo   = (const float*)d_in[7];
    const float* bo   = (const float*)d_in[8];
    const float* ln1a = (const float*)d_in[9];
    const float* ln1b = (const float*)d_in[10];
    const float* W1   = (const float*)d_in[11];
    const float* b1   = (const float*)d_in[12];
    const float* W2   = (const float*)d_in[13];
    const float* b2   = (const float*)d_in[14];
    const float* ln2a = (const float*)d_in[15];
    const float* ln2b = (const float*)d_in[16];
    float* out = (float*)d_out;

    float *h1, *Vm, *ctx, *x1, *h2, *f1, *W3, *b3;
    __nv_bfloat16 *Qb, *Kb, *Vt;
    cudaGetSymbolAddress((void**)&h1,  g_h1);
    cudaGetSymbolAddress((void**)&Qb,  g_Qb);
    cudaGetSymbolAddress((void**)&Kb,  g_Kb);
    cudaGetSymbolAddress((void**)&Vm,  g_V);
    cudaGetSymbolAddress((void**)&Vt,  g_Vt);
    cudaGetSymbolAddress((void**)&ctx, g_ctx);
    cudaGetSymbolAddress((void**)&x1,  g_x1);
    cudaGetSymbolAddress((void**)&h2,  g_h2);
    cudaGetSymbolAddress((void**)&f1,  g_f1);
    cudaGetSymbolAddress((void**)&W3,  g_W3);
    cudaGetSymbolAddress((void**)&b3,  g_b3);

    cudaFuncSetAttribute(mm_tf32<false, false>,
                         cudaFuncAttributeMaxDynamicSharedMemorySize, MM_SMEM);
    cudaFuncSetAttribute(mm_tf32<false, true>,
                         cudaFuncAttributeMaxDynamicSharedMemorySize, MM_SMEM);
    cudaFuncSetAttribute(mm_tf32<true, false>,
                         cudaFuncAttributeMaxDynamicSharedMemorySize, MM_SMEM);
    cudaFuncSetAttribute(attn_bf16,
                         cudaFuncAttributeMaxDynamicSharedMemorySize, ATT_SMEM);

    concat3<<<(D_MODEL * QKV_N) / 256, 256>>>(Wq, Wk, Wv, bq, bk, bv, W3, b3);

    const dim3 gQKV (QKV_N  / 128, S_LEN / 128);     // (24, 32)
    const dim3 gSmall(D_MODEL / 128, S_LEN / 128);   // (8, 32)
    const dim3 gFF1 (D_FF   / 128, S_LEN / 128);     // (32, 32)

    // residual 1
    ln_kernel<<<S_LEN, 256>>>(x, ln1a, ln1b, h1);
    mm_tf32<false, false><<<gQKV, 256, MM_SMEM>>>(h1, W3, b3, nullptr,
        (float*)Qb, (float*)Kb, Vm, S_LEN, QKV_N, D_MODEL);
    vtrans<<<dim3(S_LEN / 64, D_MODEL / 32), 256>>>(Vm, Vt);
    attn_bf16<<<dim3(S_LEN / 128, NUM_HEADS), 128, ATT_SMEM>>>(Qb, Kb, Vt, ctx);
    mm_tf32<false, true><<<gSmall, 256, MM_SMEM>>>(ctx, Wo, bo, x,
        x1, nullptr, nullptr, S_LEN, D_MODEL, D_MODEL);

    // residual 2
    ln_kernel<<<S_LEN, 256>>>(x1, ln2a, ln2b, h2);
    mm_tf32<true,  false><<<gFF1, 256, MM_SMEM>>>(h2, W1, b1, nullptr,
        f1, nullptr, nullptr, S_LEN, D_FF, D_MODEL);
    mm_tf32<false, true><<<gSmall, 256, MM_SMEM>>>(f1, W2, b2, x1,
        out, nullptr, nullptr, S_LEN, D_MODEL, D_FF);
}

// round 9
// speedup vs baseline: 2.1791x; 1.0368x over previous
#include <cuda_runtime.h>
#include <cuda_bf16.h>
#include <math.h>
#include <stdint.h>

// ---------------------------------------------------------------------------
// Encoder layer: B=1, S=4096, D=1024, H=16, dk=64, F=4096, fp32 in/out.
// GEMMs: tf32 mma.sync, a-frags via ldmatrix.x4. Attention: bf16 m16n8k16,
// K/V/Q frags via ldmatrix, FA2 c->a packing, MUFU ex2 softmax.
// ---------------------------------------------------------------------------

#define S_LEN 4096
#define D_MODEL 1024
#define D_FF 4096
#define NUM_HEADS 16
#define DK 64
#define QKV_N 3072

__device__ float g_h1[S_LEN * D_MODEL];
__device__ __nv_bfloat16 g_Qb[S_LEN * D_MODEL];
__device__ __nv_bfloat16 g_Kb[S_LEN * D_MODEL];
__device__ float g_V [S_LEN * D_MODEL];
__device__ __nv_bfloat16 g_Vt[D_MODEL * S_LEN];   // [dim][key]
__device__ float g_ctx[S_LEN * D_MODEL];
__device__ float g_x1[S_LEN * D_MODEL];
__device__ float g_h2[S_LEN * D_MODEL];
__device__ float g_f1[S_LEN * D_FF];
__device__ float g_W3[D_MODEL * QKV_N];
__device__ float g_b3[QKV_N];

// ---------------------------------------------------------------------------
__device__ __forceinline__ void mma_tf32(float (&d)[4],
    const uint32_t (&a)[4], uint32_t b0, uint32_t b1)
{
    asm volatile(
        "mma.sync.aligned.m16n8k8.row.col.f32.tf32.tf32.f32 "
        "{%0,%1,%2,%3}, {%4,%5,%6,%7}, {%8,%9}, {%0,%1,%2,%3};\n"
        : "+f"(d[0]), "+f"(d[1]), "+f"(d[2]), "+f"(d[3])
        : "r"(a[0]), "r"(a[1]), "r"(a[2]), "r"(a[3]), "r"(b0), "r"(b1));
}
__device__ __forceinline__ void mma_bf16(float (&d)[4],
    const uint32_t (&a)[4], uint32_t b0, uint32_t b1)
{
    asm volatile(
        "mma.sync.aligned.m16n8k16.row.col.f32.bf16.bf16.f32 "
        "{%0,%1,%2,%3}, {%4,%5,%6,%7}, {%8,%9}, {%0,%1,%2,%3};\n"
        : "+f"(d[0]), "+f"(d[1]), "+f"(d[2]), "+f"(d[3])
        : "r"(a[0]), "r"(a[1]), "r"(a[2]), "r"(a[3]), "r"(b0), "r"(b1));
}
__device__ __forceinline__ void ldsm_x4(uint32_t (&d)[4], uint32_t saddr) {
    asm volatile("ldmatrix.sync.aligned.m8n8.x4.shared.b16 {%0,%1,%2,%3}, [%4];"
        : "=r"(d[0]), "=r"(d[1]), "=r"(d[2]), "=r"(d[3]) : "r"(saddr));
}
__device__ __forceinline__ void ldsm_x2(uint32_t& d0, uint32_t& d1, uint32_t saddr) {
    asm volatile("ldmatrix.sync.aligned.m8n8.x2.shared.b16 {%0,%1}, [%2];"
        : "=r"(d0), "=r"(d1) : "r"(saddr));
}
__device__ __forceinline__ uint32_t f2u(float x) { return __float_as_uint(x); }
__device__ __forceinline__ uint32_t smem_u32(const void* p) {
    return (uint32_t)__cvta_generic_to_shared(p);
}
__device__ __forceinline__ uint32_t pack_bf16(float lo, float hi) {
    __nv_bfloat162 v = __floats2bfloat162_rn(lo, hi);
    return *(uint32_t*)&v;
}
#define CP_ASYNC16(dst, src) \
    asm volatile("cp.async.cg.shared.global [%0], [%1], 16;\n" :: "r"(dst), "l"(src))
#define CP_COMMIT() asm volatile("cp.async.commit_group;\n")
#define CP_WAIT(n)  asm volatile("cp.async.wait_group %0;\n" :: "n"(n))

__device__ __forceinline__ float ex2(float x) {
    float y;
    asm("ex2.approx.f32 %0, %1;" : "=f"(y) : "f"(x));
    return y;
}

// ---------------------------------------------------------------------------
// Concat Wq|Wk|Wv -> W3 [1024, 3072], bq|bk|bv -> b3 [3072]
// ---------------------------------------------------------------------------
__global__ __launch_bounds__(256) void concat3(
    const float* __restrict__ Wq, const float* __restrict__ Wk,
    const float* __restrict__ Wv, const float* __restrict__ bq,
    const float* __restrict__ bk, const float* __restrict__ bv,
    float* __restrict__ W3, float* __restrict__ b3)
{
    const int idx = blockIdx.x * 256 + threadIdx.x;
    const int k = idx / QKV_N, n = idx % QKV_N;
    const int sel = n >> 10, col = n & 1023;
    const float* W = sel == 0 ? Wq : (sel == 1 ? Wk : Wv);
    W3[idx] = W[k * D_MODEL + col];
    if (idx < QKV_N) {
        const float* b = sel == 0 ? bq : (sel == 1 ? bk : bv);
        b3[idx] = b[col];
    }
}

// ---------------------------------------------------------------------------
// V [S,1024] fp32 -> Vt [1024,S] bf16 (transpose + convert)
// ---------------------------------------------------------------------------
__global__ __launch_bounds__(256) void vtrans(
    const float* __restrict__ V, __nv_bfloat16* __restrict__ Vt)
{
    __shared__ float t[64][33];
    const int k0 = blockIdx.x * 64;
    const int d0 = blockIdx.y * 32;
    const int x = threadIdx.x & 31;
    const int y = threadIdx.x >> 5;
#pragma unroll
    for (int i = 0; i < 64; i += 8)
        t[y + i][x] = V[(size_t)(k0 + y + i) * D_MODEL + d0 + x];
    __syncthreads();
    uint32_t* Vt32 = (uint32_t*)Vt;
#pragma unroll
    for (int p = 0; p < 4; p++) {
        const int d = y + 8 * p;
        const int j = x;
        uint32_t v = pack_bf16(t[2 * j][d], t[2 * j + 1][d]);
        Vt32[(size_t)(d0 + d) * (S_LEN / 2) + (k0 >> 1) + j] = v;
    }
}

// ---------------------------------------------------------------------------
// LayerNorm (unbiased var ddof=1, denom = sqrt(var)+eps)
// ---------------------------------------------------------------------------
__global__ __launch_bounds__(256) void ln_kernel(
    const float* __restrict__ x, const float* __restrict__ alpha,
    const float* __restrict__ beta, float* __restrict__ y)
{
    const int row = blockIdx.x;
    const float4* xr = (const float4*)(x + (size_t)row * D_MODEL);
    float4* yr = (float4*)(y + (size_t)row * D_MODEL);
    const int tid = threadIdx.x;

    float4 xl = xr[tid];
    float s = xl.x + xl.y + xl.z + xl.w;

    __shared__ float sh[8];
#pragma unroll
    for (int o = 16; o > 0; o >>= 1) s += __shfl_xor_sync(0xffffffffu, s, o);
    if ((tid & 31) == 0) sh[tid >> 5] = s;
    __syncthreads();
    float mu = 0.f;
#pragma unroll
    for (int i = 0; i < 8; i++) mu += sh[i];
    mu *= (1.0f / D_MODEL);
    __syncthreads();

    float dx = xl.x - mu, dy = xl.y - mu, dz = xl.z - mu, dw = xl.w - mu;
    float v = dx * dx + dy * dy + dz * dz + dw * dw;
#pragma unroll
    for (int o = 16; o > 0; o >>= 1) v += __shfl_xor_sync(0xffffffffu, v, o);
    if ((tid & 31) == 0) sh[tid >> 5] = v;
    __syncthreads();
    float var = 0.f;
#pragma unroll
    for (int i = 0; i < 8; i++) var += sh[i];
    var *= (1.0f / (D_MODEL - 1));

    const float a = alpha[0], b = beta[0];
    const float inv = a / (sqrtf(var) + 1e-6f);
    float4 o;
    o.x = dx * inv + b; o.y = dy * inv + b;
    o.z = dz * inv + b; o.w = dw * inv + b;
    yr[tid] = o;
}

// ---------------------------------------------------------------------------
// TF32 GEMM: C = A[M,K] @ W[K,N] + bias (+relu) (+residual)
// BM=128 BN=128 BK=32, 256 threads, 3-stage cp.async, 1 barrier/k-tile,
// 2 CTAs/SM. A-frags via ldmatrix.x4 (1 LDSM instead of 4 scalar LDS).
// QKV mode (C1 != nullptr): Q,K outputs bf16; V output fp32.
// ---------------------------------------------------------------------------
#define ASTR 36
#define BSTR 136
#define A_TILE (128 * ASTR)
#define B_TILE (32 * BSTR)
#define STG_F  (A_TILE + B_TILE)
#define MM_SMEM (3 * STG_F * 4)

template<bool RELU, bool RES>
__global__ __launch_bounds__(256, 2) void mm_tf32(
    const float* __restrict__ A, const float* __restrict__ W,
    const float* __restrict__ bias, const float* __restrict__ Rsd,
    float* __restrict__ C0, float* __restrict__ C1, float* __restrict__ C2,
    int M, int N, int K)
{
    extern __shared__ float smg[];

    const int tid  = threadIdx.x;
    const int warp = tid >> 5, lane = tid & 31;
    const int r = lane >> 2, c = lane & 3;
    const int wm = (warp >> 2) * 64, wn = (warp & 3) * 32;
    const int m0 = blockIdx.y * 128, n0 = blockIdx.x * 128;

    const uint32_t s0 = smem_u32(smg);

    // ldmatrix lane addressing: matrix = lane>>3, row-in-matrix = lane&7
    const int g2 = lane >> 3, rowin = lane & 7;
    // byte offset of this lane's ldsm row within the warp's A sub-tile
    const uint32_t aLane = (uint32_t)((((g2 & 1) * 8 + rowin) * ASTR + (g2 >> 1) * 4) * 4);

    float acc[4][4][4];
#pragma unroll
    for (int i = 0; i < 4; i++)
#pragma unroll
        for (int j = 0; j < 4; j++)
#pragma unroll
            for (int k = 0; k < 4; k++) acc[i][j][k] = 0.f;

    const int NK = K >> 5;

    auto load_tile = [&](int kt, int st) {
        const uint32_t ab = s0 + (uint32_t)(st * STG_F) * 4u;
        const uint32_t bb = ab + (uint32_t)A_TILE * 4u;
#pragma unroll
        for (int i = 0; i < 4; i++) {
            const int id = tid + 256 * i;
            const int ar = id >> 3, akc = id & 7;
            CP_ASYNC16(ab + (uint32_t)(ar * ASTR + akc * 4) * 4u,
                       A + (size_t)(m0 + ar) * K + kt * 32 + akc * 4);
            const int br = id >> 5, bnc = id & 31;
            CP_ASYNC16(bb + (uint32_t)(br * BSTR + bnc * 4) * 4u,
                       W + (size_t)(kt * 32 + br) * N + n0 + bnc * 4);
        }
    };

    load_tile(0, 0);
    CP_COMMIT();
    load_tile(1, 1);
    CP_COMMIT();

    for (int kt = 0; kt < NK; kt++) {
        const int st = kt - (kt / 3) * 3;
        CP_WAIT(1);
        __syncthreads();
        if (kt + 2 < NK) {
            const int s2 = (kt + 2) - ((kt + 2) / 3) * 3;
            load_tile(kt + 2, s2);
        }
        CP_COMMIT();

        const uint32_t aWarp = s0 + (uint32_t)(st * STG_F + wm * ASTR) * 4u + aLane;
        const float* Bb = smg + st * STG_F + A_TILE;
#pragma unroll
        for (int ks = 0; ks < 4; ks++) {
            uint32_t a[4][4], b[4][2];
#pragma unroll
            for (int fm = 0; fm < 4; fm++)
                ldsm_x4(a[fm], aWarp + (uint32_t)((fm * 16 * ASTR + ks * 8) * 4));
#pragma unroll
            for (int fn = 0; fn < 4; fn++) {
                const float* q = Bb + (ks * 8 + c) * BSTR + wn + fn * 8 + r;
                b[fn][0] = f2u(q[0]);
                b[fn][1] = f2u(q[4 * BSTR]);
            }
#pragma unroll
            for (int fm = 0; fm < 4; fm++)
#pragma unroll
                for (int fn = 0; fn < 4; fn++)
                    mma_tf32(acc[fm][fn], a[fm], b[fn][0], b[fn][1]);
        }
    }

    if (C1 != nullptr) {
        const int sel = n0 >> 10;
        const int nl0 = n0 & 1023;
        if (sel < 2) {
            __nv_bfloat16* Cb = (__nv_bfloat16*)(sel == 0 ? (void*)C0 : (void*)C1);
#pragma unroll
            for (int fm = 0; fm < 4; fm++) {
                const int row0 = m0 + wm + fm * 16 + r;
                const int row1 = row0 + 8;
#pragma unroll
                for (int fn = 0; fn < 4; fn++) {
                    const int colg = n0 + wn + fn * 8 + 2 * c;
                    const int col  = nl0 + wn + fn * 8 + 2 * c;
                    float2 bi = *(const float2*)&bias[colg];
                    uint32_t p0 = pack_bf16(acc[fm][fn][0] + bi.x, acc[fm][fn][1] + bi.y);
                    uint32_t p1 = pack_bf16(acc[fm][fn][2] + bi.x, acc[fm][fn][3] + bi.y);
                    *(uint32_t*)&Cb[(size_t)row0 * 1024 + col] = p0;
                    *(uint32_t*)&Cb[(size_t)row1 * 1024 + col] = p1;
                }
            }
        } else {
#pragma unroll
            for (int fm = 0; fm < 4; fm++) {
                const int row0 = m0 + wm + fm * 16 + r;
                const int row1 = row0 + 8;
#pragma unroll
                for (int fn = 0; fn < 4; fn++) {
                    const int colg = n0 + wn + fn * 8 + 2 * c;
                    const int col  = nl0 + wn + fn * 8 + 2 * c;
                    float2 bi = *(const float2*)&bias[colg];
                    *(float2*)&C2[(size_t)row0 * 1024 + col] =
                        make_float2(acc[fm][fn][0] + bi.x, acc[fm][fn][1] + bi.y);
                    *(float2*)&C2[(size_t)row1 * 1024 + col] =
                        make_float2(acc[fm][fn][2] + bi.x, acc[fm][fn][3] + bi.y);
                }
            }
        }
        return;
    }

#pragma unroll
    for (int fm = 0; fm < 4; fm++) {
        const int row0 = m0 + wm + fm * 16 + r;
        const int row1 = row0 + 8;
#pragma unroll
        for (int fn = 0; fn < 4; fn++) {
            const int col = n0 + wn + fn * 8 + 2 * c;
            float2 bi = *(const float2*)&bias[col];
            float v0 = acc[fm][fn][0] + bi.x;
            float v1 = acc[fm][fn][1] + bi.y;
            float v2 = acc[fm][fn][2] + bi.x;
            float v3 = acc[fm][fn][3] + bi.y;
            if (RELU) {
                v0 = fmaxf(v0, 0.f); v1 = fmaxf(v1, 0.f);
                v2 = fmaxf(v2, 0.f); v3 = fmaxf(v3, 0.f);
            }
            if (RES) {
                float2 r0 = *(const float2*)&Rsd[(size_t)row0 * N + col];
                float2 r1 = *(const float2*)&Rsd[(size_t)row1 * N + col];
                v0 += r0.x; v1 += r0.y; v2 += r1.x; v3 += r1.y;
            }
            *(float2*)&C0[(size_t)row0 * N + col] = make_float2(v0, v1);
            *(float2*)&C0[(size_t)row1 * N + col] = make_float2(v2, v3);
        }
    }
}

// ---------------------------------------------------------------------------
// Flash attention, bf16 m16n8k16. grid = (S/128, H), 128 threads, 2 CTAs/SM.
// Warp owns 32 q-rows. Q frags reloaded per-iter via ldmatrix.x4 (saves 32
// persistent regs); K/V b-frags via ldmatrix.x2. FA2 c->a packing via
// cvt.rn.bf16x2. MUFU ex2 softmax, scale folded into exp FMA.
// ---------------------------------------------------------------------------
#define ASTRU 36
#define QTILE_U (128 * ASTRU)
#define KTILE_U (64 * ASTRU)
#define ATT_SMEM ((QTILE_U + 4 * KTILE_U) * 4)
#define QK_SCALE 0.1803368801111364f       // 0.125 * log2(e)

__global__ __launch_bounds__(128, 2) void attn_bf16(
    const __nv_bfloat16* __restrict__ Qm, const __nv_bfloat16* __restrict__ Km,
    const __nv_bfloat16* __restrict__ Vt, float* __restrict__ Ctx)
{
    extern __shared__ uint32_t su[];
    uint32_t* Qs = su;                     // [128][36]
    uint32_t* Ks = Qs + QTILE_U;           // [2][64][36]
    uint32_t* Vs = Ks + 2 * KTILE_U;       // [2][64][36]

    const int tid  = threadIdx.x;
    const int warp = tid >> 5, lane = tid & 31;
    const int r = lane >> 2, c = lane & 3;
    const int wr = warp * 32;
    const int qb = blockIdx.x, h = blockIdx.y;
    const int cb = h * DK;

    const uint32_t qdst = smem_u32(Qs);
    const uint32_t kdst = smem_u32(Ks);
    const uint32_t vdst = smem_u32(Vs);

    // ldmatrix lane addressing
    const int g2 = lane >> 3, rowin = lane & 7;
    // x4 (Q a-frags): matrix (g2&1)->row+8, (g2>>1)->col+4 u32
    const uint32_t qLane = (uint32_t)(((g2 & 1) * 8 + rowin) * ASTRU + (g2 >> 1) * 4) * 4u;
    // x2 (K/V b-frags): matrix (g2&1)->col+4 u32
    const uint32_t kLane = (uint32_t)(rowin * ASTRU + (g2 & 1) * 4) * 4u;

    // stage Q (128 rows x 64 dims bf16) + K/V tile 0
#pragma unroll
    for (int i = 0; i < 8; i++) {
        int id = tid + 128 * i;
        int row = id >> 3, ch = id & 7;
        CP_ASYNC16(qdst + (uint32_t)(row * ASTRU + ch * 4) * 4u,
                   Qm + (size_t)(qb * 128 + row) * D_MODEL + cb + ch * 8);
    }
#pragma unroll
    for (int i = 0; i < 4; i++) {
        int id = tid + 128 * i;
        int row = id >> 3, ch = id & 7;
        CP_ASYNC16(kdst + (uint32_t)(row * ASTRU + ch * 4) * 4u,
                   Km + (size_t)row * D_MODEL + cb + ch * 8);
        CP_ASYNC16(vdst + (uint32_t)(row * ASTRU + ch * 4) * 4u,
                   Vt + (size_t)(cb + row) * S_LEN + ch * 8);
    }
    CP_COMMIT();
    CP_WAIT(0);
    __syncthreads();

    const uint32_t qWarp = qdst + (uint32_t)(wr * ASTRU) * 4u + qLane;

    float mrow[2][2] = {{-1e30f, -1e30f}, {-1e30f, -1e30f}};
    float lrow[2][2] = {{0.f, 0.f}, {0.f, 0.f}};
    float acc[2][8][4];
#pragma unroll
    for (int i = 0; i < 2; i++)
#pragma unroll
        for (int j = 0; j < 8; j++)
#pragma unroll
            for (int k = 0; k < 4; k++) acc[i][j][k] = 0.f;

    for (int kt = 0; kt < S_LEN / 64; kt++) {
        const int buf = kt & 1;

        if (kt > 0) {
            CP_WAIT(0);
            __syncthreads();
        }
        if (kt + 1 < S_LEN / 64) {
            const int nb = buf ^ 1;
#pragma unroll
            for (int i = 0; i < 4; i++) {
                int id = tid + 128 * i;
                int row = id >> 3, ch = id & 7;
                CP_ASYNC16(kdst + (uint32_t)(nb * KTILE_U + row * ASTRU + ch * 4) * 4u,
                           Km + (size_t)((kt + 1) * 64 + row) * D_MODEL + cb + ch * 8);
                CP_ASYNC16(vdst + (uint32_t)(nb * KTILE_U + row * ASTRU + ch * 4) * 4u,
                           Vt + (size_t)(cb + row) * S_LEN + (kt + 1) * 64 + ch * 8);
            }
            CP_COMMIT();
        }

        // ---- S = Q @ K^T : m32 x n64 x k64 (4 k16 blocks) ----
        float s[2][8][4];
#pragma unroll
        for (int i = 0; i < 2; i++)
#pragma unroll
            for (int j = 0; j < 8; j++)
#pragma unroll
                for (int k = 0; k < 4; k++) s[i][j][k] = 0.f;

        const uint32_t kTile = kdst + (uint32_t)(buf * KTILE_U) * 4u + kLane;
#pragma unroll
        for (int ks = 0; ks < 4; ks++) {
            uint32_t qf0[4], qf1[4];
            ldsm_x4(qf0, qWarp + (uint32_t)((ks * 8) * 4));
            ldsm_x4(qf1, qWarp + (uint32_t)((16 * ASTRU + ks * 8) * 4));
#pragma unroll
            for (int fn = 0; fn < 8; fn++) {
                uint32_t b0, b1;
                ldsm_x2(b0, b1, kTile + (uint32_t)((8 * fn * ASTRU + ks * 8) * 4));
                mma_bf16(s[0][fn], qf0, b0, b1);
                mma_bf16(s[1][fn], qf1, b0, b1);
            }
        }

        // ---- online softmax (raw domain; scale folded into exp fma) ----
        uint32_t pa[2][4][4];
#pragma unroll
        for (int fm = 0; fm < 2; fm++) {
            float mx0 = -1e30f, mx1 = -1e30f;
#pragma unroll
            for (int fn = 0; fn < 8; fn++) {
                mx0 = fmaxf(mx0, fmaxf(s[fm][fn][0], s[fm][fn][1]));
                mx1 = fmaxf(mx1, fmaxf(s[fm][fn][2], s[fm][fn][3]));
            }
            mx0 = fmaxf(mx0, __shfl_xor_sync(0xffffffffu, mx0, 1));
            mx0 = fmaxf(mx0, __shfl_xor_sync(0xffffffffu, mx0, 2));
            mx1 = fmaxf(mx1, __shfl_xor_sync(0xffffffffu, mx1, 1));
            mx1 = fmaxf(mx1, __shfl_xor_sync(0xffffffffu, mx1, 2));

            const float mn0 = fmaxf(mrow[fm][0], mx0);
            const float mn1 = fmaxf(mrow[fm][1], mx1);
            const float emn0 = mn0 * QK_SCALE;
            const float emn1 = mn1 * QK_SCALE;
            const float sc0 = ex2(fmaf(mrow[fm][0], QK_SCALE, -emn0));
            const float sc1 = ex2(fmaf(mrow[fm][1], QK_SCALE, -emn1));
            float ls0 = 0.f, ls1 = 0.f;
#pragma unroll
            for (int fn = 0; fn < 8; fn++) {
                float e0 = ex2(fmaf(s[fm][fn][0], QK_SCALE, -emn0));
                float e1 = ex2(fmaf(s[fm][fn][1], QK_SCALE, -emn0));
                float e2 = ex2(fmaf(s[fm][fn][2], QK_SCALE, -emn1));
                float e3 = ex2(fmaf(s[fm][fn][3], QK_SCALE, -emn1));
                ls0 += e0 + e1;
                ls1 += e2 + e3;
                pa[fm][fn >> 1][(fn & 1) * 2 + 0] = pack_bf16(e0, e1);
                pa[fm][fn >> 1][(fn & 1) * 2 + 1] = pack_bf16(e2, e3);
            }
            ls0 += __shfl_xor_sync(0xffffffffu, ls0, 1);
            ls0 += __shfl_xor_sync(0xffffffffu, ls0, 2);
            ls1 += __shfl_xor_sync(0xffffffffu, ls1, 1);
            ls1 += __shfl_xor_sync(0xffffffffu, ls1, 2);

            lrow[fm][0] = lrow[fm][0] * sc0 + ls0;
            lrow[fm][1] = lrow[fm][1] * sc1 + ls1;
            mrow[fm][0] = mn0; mrow[fm][1] = mn1;

#pragma unroll
            for (int fn = 0; fn < 8; fn++) {
                acc[fm][fn][0] *= sc0; acc[fm][fn][1] *= sc0;
                acc[fm][fn][2] *= sc1; acc[fm][fn][3] *= sc1;
            }
        }

        // ---- O += P @ V ----
        const uint32_t vTile = vdst + (uint32_t)(buf * KTILE_U) * 4u + kLane;
#pragma unroll
        for (int ks = 0; ks < 4; ks++) {
#pragma unroll
            for (int fn = 0; fn < 8; fn++) {
                uint32_t b0, b1;
                ldsm_x2(b0, b1, vTile + (uint32_t)((8 * fn * ASTRU + ks * 8) * 4));
                mma_bf16(acc[0][fn], pa[0][ks], b0, b1);
                mma_bf16(acc[1][fn], pa[1][ks], b0, b1);
            }
        }
    }

    // epilogue: normalize + store
#pragma unroll
    for (int fm = 0; fm < 2; fm++) {
        const float inv0 = 1.f / lrow[fm][0];
        const float inv1 = 1.f / lrow[fm][1];
        const int row0 = qb * 128 + wr + fm * 16 + r;
        const int row1 = row0 + 8;
#pragma unroll
        for (int fn = 0; fn < 8; fn++) {
            const int col = cb + fn * 8 + 2 * c;
            *(float2*)&Ctx[(size_t)row0 * D_MODEL + col] =
                make_float2(acc[fm][fn][0] * inv0, acc[fm][fn][1] * inv0);
            *(float2*)&Ctx[(size_t)row1 * D_MODEL + col] =
                make_float2(acc[fm][fn][2] * inv1, acc[fm][fn][3] * inv1);
        }
    }
}

// ---------------------------------------------------------------------------
extern "C" void kernel_launch(void* const* d_in, const int* in_sizes, int n_in,
                              void* d_out, int out_size)
{
    const float* x    = (const float*)d_in[0];
    const float* Wq   = (const float*)d_in[1];
    const float* bq   = (const float*)d_in[2];
    const float* Wk   = (const float*)d_in[3];
    const float* bk   = (const float*)d_in[4];
    const float* Wv   = (const float*)d_in[5];
    const float* bv   = (const float*)d_in[6];
    const float* Wo   = (const float*)d_in[7];
    const float* bo   = (const float*)d_in[8];
    const float* ln1a = (const float*)d_in[9];
    const float* ln1b = (const float*)d_in[10];
    const float* W1   = (const float*)d_in[11];
    const float* b1   = (const float*)d_in[12];
    const float* W2   = (const float*)d_in[13];
    const float* b2   = (const float*)d_in[14];
    const float* ln2a = (const float*)d_in[15];
    const float* ln2b = (const float*)d_in[16];
    float* out = (float*)d_out;

    float *h1, *Vm, *ctx, *x1, *h2, *f1, *W3, *b3;
    __nv_bfloat16 *Qb, *Kb, *Vt;
    cudaGetSymbolAddress((void**)&h1,  g_h1);
    cudaGetSymbolAddress((void**)&Qb,  g_Qb);
    cudaGetSymbolAddress((void**)&Kb,  g_Kb);
    cudaGetSymbolAddress((void**)&Vm,  g_V);
    cudaGetSymbolAddress((void**)&Vt,  g_Vt);
    cudaGetSymbolAddress((void**)&ctx, g_ctx);
    cudaGetSymbolAddress((void**)&x1,  g_x1);
    cudaGetSymbolAddress((void**)&h2,  g_h2);
    cudaGetSymbolAddress((void**)&f1,  g_f1);
    cudaGetSymbolAddress((void**)&W3,  g_W3);
    cudaGetSymbolAddress((void**)&b3,  g_b3);

    cudaFuncSetAttribute(mm_tf32<false, false>,
                         cudaFuncAttributeMaxDynamicSharedMemorySize, MM_SMEM);
    cudaFuncSetAttribute(mm_tf32<false, true>,
                         cudaFuncAttributeMaxDynamicSharedMemorySize, MM_SMEM);
    cudaFuncSetAttribute(mm_tf32<true, false>,
                         cudaFuncAttributeMaxDynamicSharedMemorySize, MM_SMEM);
    cudaFuncSetAttribute(attn_bf16,
                         cudaFuncAttributeMaxDynamicSharedMemorySize, ATT_SMEM);

    concat3<<<(D_MODEL * QKV_N) / 256, 256>>>(Wq, Wk, Wv, bq, bk, bv, W3, b3);

    const dim3 gQKV (QKV_N  / 128, S_LEN / 128);     // (24, 32)
    const dim3 gSmall(D_MODEL / 128, S_LEN / 128);   // (8, 32)
    const dim3 gFF1 (D_FF   / 128, S_LEN / 128);     // (32, 32)

    // residual 1
    ln_kernel<<<S_LEN, 256>>>(x, ln1a, ln1b, h1);
    mm_tf32<false, false><<<gQKV, 256, MM_SMEM>>>(h1, W3, b3, nullptr,
        (float*)Qb, (float*)Kb, Vm, S_LEN, QKV_N, D_MODEL);
    vtrans<<<dim3(S_LEN / 64, D_MODEL / 32), 256>>>(Vm, Vt);
    attn_bf16<<<dim3(S_LEN / 128, NUM_HEADS), 128, ATT_SMEM>>>(Qb, Kb, Vt, ctx);
    mm_tf32<false, true><<<gSmall, 256, MM_SMEM>>>(ctx, Wo, bo, x,
        x1, nullptr, nullptr, S_LEN, D_MODEL, D_MODEL);

    // residual 2
    ln_kernel<<<S_LEN, 256>>>(x1, ln2a, ln2b, h2);
    mm_tf32<true,  false><<<gFF1, 256, MM_SMEM>>>(h2, W1, b1, nullptr,
        f1, nullptr, nullptr, S_LEN, D_FF, D_MODEL);
    mm_tf32<false, true><<<gSmall, 256, MM_SMEM>>>(f1, W2, b2, x1,
        out, nullptr, nullptr, S_LEN, D_MODEL, D_FF);
}